// round 13
// baseline (speedup 1.0000x reference)
#include <cuda_runtime.h>
#include <cuda_bf16.h>
#include <math.h>
#include <stdint.h>

// Problem constants
#define L   16384
#define E   131072
#define SP  20000
#define C   512
#define H   8
#define DH  64
#define HID 1024
#define NQKV 1536

// ---------------- scratch (device globals: allocation-free) ----------------
__device__ __nv_bfloat16 g_z[(size_t)L * C];
__device__ __nv_bfloat16 g_qb[(size_t)L * C];
__device__ __nv_bfloat16 g_kb[(size_t)L * C];
__device__ __nv_bfloat16 g_vb[(size_t)L * C];
__device__ __nv_bfloat16 g_agg[(size_t)L * C];
__device__ float         g_x1[(size_t)L * C];
__device__ __nv_bfloat16 g_z2[(size_t)L * C];
__device__ __nv_bfloat16 g_hid[(size_t)L * HID];
// transposed bf16 weights: [N][K]
__device__ __nv_bfloat16 g_wqkv[(size_t)NQKV * C];
__device__ float         g_bqkv[NQKV];
__device__ __nv_bfloat16 g_wo[(size_t)C * C];
__device__ __nv_bfloat16 g_w1[(size_t)HID * C];
__device__ __nv_bfloat16 g_w2[(size_t)C * HID];
// CSR
__device__ int g_cnt[L];
__device__ int g_off[L + 1];
__device__ int g_cur[L];
__device__ int g_eid[E];

// ---------------- helpers ----------------
__device__ __forceinline__ float gelu_tanh(float x) {
    const float k0 = 0.7978845608028654f;
    const float k1 = 0.044715f;
    float x3 = x * x * x;
    return 0.5f * x * (1.0f + tanhf(k0 * (x + k1 * x3)));
}

__device__ __forceinline__ void mma_bf16(float* d, const uint32_t* a,
                                         const uint32_t* b) {
    asm volatile(
        "mma.sync.aligned.m16n8k16.row.col.f32.bf16.bf16.f32 "
        "{%0,%1,%2,%3}, {%4,%5,%6,%7}, {%8,%9}, {%0,%1,%2,%3};\n"
        : "+f"(d[0]), "+f"(d[1]), "+f"(d[2]), "+f"(d[3])
        : "r"(a[0]), "r"(a[1]), "r"(a[2]), "r"(a[3]),
          "r"(b[0]), "r"(b[1]));
}

__device__ __forceinline__ void ldsm_x4(uint32_t* r, uint32_t addr) {
    asm volatile(
        "ldmatrix.sync.aligned.m8n8.x4.shared.b16 {%0,%1,%2,%3}, [%4];\n"
        : "=r"(r[0]), "=r"(r[1]), "=r"(r[2]), "=r"(r[3]) : "r"(addr));
}

__device__ __forceinline__ void cp16(uint32_t dst, const void* src) {
    asm volatile("cp.async.cg.shared.global [%0], [%1], 16;\n"
                 :: "r"(dst), "l"(src));
}
__device__ __forceinline__ void cp_commit() {
    asm volatile("cp.async.commit_group;\n");
}
template <int N>
__device__ __forceinline__ void cp_wait() {
    asm volatile("cp.async.wait_group %0;\n" :: "n"(N));
}
__device__ __forceinline__ uint32_t smem_u32(const void* p) {
    uint32_t a;
    asm("{ .reg .u64 t; cvta.to.shared.u64 t, %1; cvt.u32.u64 %0, t; }"
        : "=r"(a) : "l"(p));
    return a;
}

// unpack uint4 (8 bf16) into 8 floats
__device__ __forceinline__ void unpack8(const uint4& u, float* f) {
    float2 t;
    t = __bfloat1622float2(*(const __nv_bfloat162*)&u.x); f[0] = t.x; f[1] = t.y;
    t = __bfloat1622float2(*(const __nv_bfloat162*)&u.y); f[2] = t.x; f[3] = t.y;
    t = __bfloat1622float2(*(const __nv_bfloat162*)&u.z); f[4] = t.x; f[5] = t.y;
    t = __bfloat1622float2(*(const __nv_bfloat162*)&u.w); f[6] = t.x; f[7] = t.y;
}

// swizzled byte offset of 16B chunk c (0..3) in logical row r
__device__ __forceinline__ uint32_t sw_off(int r, int c) {
    return (uint32_t)((r >> 1) * 128 + ((((c + 4 * (r & 1))) ^ ((r >> 1) & 7)) << 4));
}

// ---------------- weight prep: 3 transposes per launch + bias pack --------
// zbase=0: planes 0..2 (Wq,Wk,Wv -> wqkv) + bias pack
// zbase=3: planes 3..5 (Wo, W1, W2)
__global__ void transpose3_kernel(const float* __restrict__ Wq,
                                  const float* __restrict__ Wk,
                                  const float* __restrict__ Wv,
                                  const float* __restrict__ Wo,
                                  const float* __restrict__ W1,
                                  const float* __restrict__ W2,
                                  const float* __restrict__ bq,
                                  const float* __restrict__ bk,
                                  const float* __restrict__ bv,
                                  __nv_bfloat16* __restrict__ wqkv,
                                  __nv_bfloat16* __restrict__ wo,
                                  __nv_bfloat16* __restrict__ w1,
                                  __nv_bfloat16* __restrict__ w2,
                                  float* __restrict__ bqkv,
                                  int zbase) {
    int z = zbase + blockIdx.z;
    if (z == 0) {
        int bid = blockIdx.y * gridDim.x + blockIdx.x;
        int i = bid * 256 + threadIdx.y * 32 + threadIdx.x;
        if (i < C) {
            bqkv[i]         = bq[i];
            bqkv[C + i]     = bk[i];
            bqkv[2 * C + i] = bv[i];
        }
    }
    const float* src;
    __nv_bfloat16* dst;
    int Kd, Nd;
    if (z == 0)      { src = Wq; dst = wqkv;                     Kd = C;   Nd = C; }
    else if (z == 1) { src = Wk; dst = wqkv + (size_t)C * C;     Kd = C;   Nd = C; }
    else if (z == 2) { src = Wv; dst = wqkv + (size_t)2 * C * C; Kd = C;   Nd = C; }
    else if (z == 3) { src = Wo; dst = wo;                       Kd = C;   Nd = C; }
    else if (z == 4) { src = W1; dst = w1;                       Kd = C;   Nd = HID; }
    else             { src = W2; dst = w2;                       Kd = HID; Nd = C; }
    int kb = blockIdx.y * 32, nb = blockIdx.x * 32;
    if (kb >= Kd || nb >= Nd) return;
    __shared__ float tile[32][33];
    int tx = threadIdx.x, ty = threadIdx.y;   // 32x8
    #pragma unroll
    for (int i = ty; i < 32; i += 8)
        tile[i][tx] = src[(size_t)(kb + i) * Nd + nb + tx];
    __syncthreads();
    #pragma unroll
    for (int i = ty; i < 32; i += 8)
        dst[(size_t)(nb + i) * Kd + kb + tx] = __float2bfloat16_rn(tile[tx][i]);
}

// ---------------- LayerNorm (bf16 output) ----------------
__global__ void ln_kernel(const float* __restrict__ x,
                          const float* __restrict__ g,
                          const float* __restrict__ b,
                          __nv_bfloat16* __restrict__ z) {
    int row = blockIdx.x;
    int t = threadIdx.x;                 // 0..127
    const float* xr = x + (size_t)row * C;
    float4 v4 = *(const float4*)(xr + t * 4);
    float s  = v4.x + v4.y + v4.z + v4.w;
    float ss = v4.x * v4.x + v4.y * v4.y + v4.z * v4.z + v4.w * v4.w;
    #pragma unroll
    for (int o = 16; o > 0; o >>= 1) {
        s  += __shfl_xor_sync(0xffffffffu, s, o);
        ss += __shfl_xor_sync(0xffffffffu, ss, o);
    }
    __shared__ float sh[4], sh2[4];
    int w = t >> 5;
    if ((t & 31) == 0) { sh[w] = s; sh2[w] = ss; }
    __syncthreads();
    float sum  = sh[0] + sh[1] + sh[2] + sh[3];
    float sum2 = sh2[0] + sh2[1] + sh2[2] + sh2[3];
    float mean = sum * (1.0f / C);
    float var  = sum2 * (1.0f / C) - mean * mean;
    float inv  = rsqrtf(var + 1e-5f);
    float4 g4 = *(const float4*)(g + t * 4);
    float4 b4 = *(const float4*)(b + t * 4);
    __nv_bfloat162 p0 = __floats2bfloat162_rn(
        (v4.x - mean) * inv * g4.x + b4.x, (v4.y - mean) * inv * g4.y + b4.y);
    __nv_bfloat162 p1 = __floats2bfloat162_rn(
        (v4.z - mean) * inv * g4.z + b4.z, (v4.w - mean) * inv * g4.w + b4.w);
    __nv_bfloat162* zr = (__nv_bfloat162*)(z + (size_t)row * C);
    zr[t * 2]     = p0;
    zr[t * 2 + 1] = p1;
}

// ---------------- bf16 tensor-core GEMM ----------------
// EPI: 1 bias+gelu->bf16, 2 bias+residual->fp32, 3 bias->bf16 q/k/v planes
#define BM  128
#define BN  128
#define BK  32
#define STAGES 4
#define STAGE_BYTES 8192
#define SMEM_BYTES (STAGES * 2 * STAGE_BYTES)   // 65536

template <int EPI>
__global__ __launch_bounds__(256, 2)
void tgemm_kernel(const __nv_bfloat16* __restrict__ A,
                  const __nv_bfloat16* __restrict__ B,
                  const float* __restrict__ bias, const float* __restrict__ res,
                  float* __restrict__ Cmat,
                  __nv_bfloat16* __restrict__ qb,
                  __nv_bfloat16* __restrict__ kb,
                  __nv_bfloat16* __restrict__ vb,
                  int M, int N, int K) {
    extern __shared__ float smemf[];
    const uint32_t sA = smem_u32(smemf);
    const uint32_t sB = sA + STAGES * STAGE_BYTES;

    const int tid    = threadIdx.x;
    const int lane   = tid & 31;
    const int wid    = tid >> 5;
    const int warp_m = wid & 3;
    const int warp_n = wid >> 2;

    const int brow = blockIdx.y * BM;
    const int bcol = blockIdx.x * BN;

    float acc[2][8][4];
    #pragma unroll
    for (int i = 0; i < 2; i++)
        #pragma unroll
        for (int j = 0; j < 8; j++)
            #pragma unroll
            for (int c = 0; c < 4; c++) acc[i][j][c] = 0.0f;

    const int lr = tid >> 1;
    const int c0 = (tid & 1) * 2;
    const __nv_bfloat16* A0 = A + (size_t)(brow + lr) * K + c0 * 8;
    const __nv_bfloat16* B0 = B + (size_t)(bcol + lr) * K + c0 * 8;
    const uint32_t dA0 = sA + sw_off(lr, c0);
    const uint32_t dA1 = sA + sw_off(lr, c0 + 1);
    const uint32_t dB0 = sB + sw_off(lr, c0);
    const uint32_t dB1 = sB + sw_off(lr, c0 + 1);

    const int m8    = lane >> 3;
    const int rowin = lane & 7;
    int rA[2], cAh = m8 >> 1;
    rA[0] = warp_m * 32 + (m8 & 1) * 8 + rowin;
    rA[1] = rA[0] + 16;
    int rB[4], cBh = m8 & 1;
    #pragma unroll
    for (int np = 0; np < 4; np++)
        rB[np] = warp_n * 64 + np * 16 + (m8 >> 1) * 8 + rowin;

    const int kIters = K / BK;

    #pragma unroll
    for (int s = 0; s < STAGES - 1; s++) {
        int k0 = s * BK;
        uint32_t so = (uint32_t)s * STAGE_BYTES;
        cp16(dA0 + so, A0 + k0);
        cp16(dA1 + so, A0 + k0 + 8);
        cp16(dB0 + so, B0 + k0);
        cp16(dB1 + so, B0 + k0 + 8);
        cp_commit();
    }

    int buf = 0;
    int nbuf = STAGES - 1;
    for (int s = 0; s < kIters; s++) {
        cp_wait<STAGES - 2>();
        __syncthreads();

        if (s + STAGES - 1 < kIters) {
            int k0 = (s + STAGES - 1) * BK;
            uint32_t so = (uint32_t)nbuf * STAGE_BYTES;
            cp16(dA0 + so, A0 + k0);
            cp16(dA1 + so, A0 + k0 + 8);
            cp16(dB0 + so, B0 + k0);
            cp16(dB1 + so, B0 + k0 + 8);
        }
        cp_commit();

        const uint32_t aBuf = sA + (uint32_t)buf * STAGE_BYTES;
        const uint32_t bBuf = sB + (uint32_t)buf * STAGE_BYTES;
        #pragma unroll
        for (int ks = 0; ks < 2; ks++) {
            uint32_t af[2][4];
            #pragma unroll
            for (int mt = 0; mt < 2; mt++)
                ldsm_x4(af[mt], aBuf + sw_off(rA[mt], 2 * ks + cAh));
            #pragma unroll
            for (int np = 0; np < 4; np++) {
                uint32_t bf[4];
                ldsm_x4(bf, bBuf + sw_off(rB[np], 2 * ks + cBh));
                mma_bf16(acc[0][2 * np],     af[0], bf);
                mma_bf16(acc[1][2 * np],     af[1], bf);
                mma_bf16(acc[0][2 * np + 1], af[0], bf + 2);
                mma_bf16(acc[1][2 * np + 1], af[1], bf + 2);
            }
        }
        buf = (buf + 1 == STAGES) ? 0 : buf + 1;
        nbuf = (nbuf + 1 == STAGES) ? 0 : nbuf + 1;
    }

    const int grp = lane >> 2;
    const int t4  = lane & 3;
    #pragma unroll
    for (int mt = 0; mt < 2; mt++) {
        int row = brow + warp_m * 32 + mt * 16 + grp;
        #pragma unroll
        for (int nt = 0; nt < 8; nt++) {
            int col = bcol + warp_n * 64 + nt * 8 + 2 * t4;
            float b0 = bias[col], b1 = bias[col + 1];
            float v0 = acc[mt][nt][0] + b0;
            float v1 = acc[mt][nt][1] + b1;
            float v2 = acc[mt][nt][2] + b0;
            float v3 = acc[mt][nt][3] + b1;
            if (EPI == 1) {
                __nv_bfloat16* O = (__nv_bfloat16*)Cmat;
                __nv_bfloat162 o0 = __floats2bfloat162_rn(gelu_tanh(v0),
                                                          gelu_tanh(v1));
                __nv_bfloat162 o1 = __floats2bfloat162_rn(gelu_tanh(v2),
                                                          gelu_tanh(v3));
                *(__nv_bfloat162*)&O[(size_t)row * N + col]       = o0;
                *(__nv_bfloat162*)&O[(size_t)(row + 8) * N + col] = o1;
            } else if (EPI == 3) {
                __nv_bfloat162 p0 = __floats2bfloat162_rn(v0, v1);
                __nv_bfloat162 p1 = __floats2bfloat162_rn(v2, v3);
                __nv_bfloat16* dst;
                int cc;
                if (col < C)          { dst = qb; cc = col; }
                else if (col < 2 * C) { dst = kb; cc = col - C; }
                else                  { dst = vb; cc = col - 2 * C; }
                *(__nv_bfloat162*)&dst[(size_t)row * C + cc]       = p0;
                *(__nv_bfloat162*)&dst[(size_t)(row + 8) * C + cc] = p1;
            } else {
                if (EPI == 2) {
                    v0 += res[(size_t)row * N + col];
                    v1 += res[(size_t)row * N + col + 1];
                    v2 += res[(size_t)(row + 8) * N + col];
                    v3 += res[(size_t)(row + 8) * N + col + 1];
                }
                float2 o0 = { v0, v1 };
                float2 o1 = { v2, v3 };
                *(float2*)&Cmat[(size_t)row * N + col]       = o0;
                *(float2*)&Cmat[(size_t)(row + 8) * N + col] = o1;
            }
        }
    }
}

// ---------------- CSR build ----------------
__global__ void zero_cnt_kernel(int* __restrict__ cnt) {
    int i = blockIdx.x * blockDim.x + threadIdx.x;
    if (i < L) cnt[i] = 0;
}
__global__ void hist_kernel(const int* __restrict__ row, int* __restrict__ cnt) {
    int e = blockIdx.x * blockDim.x + threadIdx.x;
    if (e < E) atomicAdd(&cnt[row[e]], 1);
}
__global__ void scan_kernel(const int* __restrict__ cnt, int* __restrict__ off,
                            int* __restrict__ cur) {
    __shared__ int ws[32];
    int tid = threadIdx.x;
    int base = tid * 16;
    int loc[16];
    int s = 0;
    #pragma unroll
    for (int i = 0; i < 16; i++) { loc[i] = s; s += cnt[base + i]; }
    int lane = tid & 31, w = tid >> 5;
    int v = s;
    #pragma unroll
    for (int o = 1; o < 32; o <<= 1) {
        int t = __shfl_up_sync(0xffffffffu, v, o);
        if (lane >= o) v += t;
    }
    if (lane == 31) ws[w] = v;
    __syncthreads();
    if (w == 0) {
        int t = ws[lane];
        #pragma unroll
        for (int o = 1; o < 32; o <<= 1) {
            int u = __shfl_up_sync(0xffffffffu, t, o);
            if (lane >= o) t += u;
        }
        ws[lane] = t;
    }
    __syncthreads();
    int excl = v - s + (w > 0 ? ws[w - 1] : 0);
    #pragma unroll
    for (int i = 0; i < 16; i++) {
        off[base + i] = excl + loc[i];
        cur[base + i] = excl + loc[i];
    }
    if (tid == 1023) off[L] = excl + s;
}
__global__ void scatter_kernel(const int* __restrict__ row,
                               int* __restrict__ cur, int* __restrict__ eid) {
    int e = blockIdx.x * blockDim.x + threadIdx.x;
    if (e < E) {
        int p = atomicAdd(&cur[row[e]], 1);
        eid[p] = e;
    }
}

// ---------------- fused edge attention: 2 rows per 256-thr block ----------
#define DMAX 64
__global__ __launch_bounds__(256)
void row_attn_kernel(const __nv_bfloat16* __restrict__ qb,
                     const __nv_bfloat16* __restrict__ kb,
                     const __nv_bfloat16* __restrict__ vb,
                     const int* __restrict__ off,
                     const int* __restrict__ eid,
                     const int* __restrict__ col_index,
                     const int* __restrict__ to_col_index,
                     const float* __restrict__ pab,
                     const float* __restrict__ dist,
                     const float* __restrict__ pos,
                     const float* __restrict__ col_pos,
                     const float* __restrict__ Wvec,
                     const float* __restrict__ bvec,
                     __nv_bfloat16* __restrict__ agg) {
    int tid  = threadIdx.x;          // 256
    int sub  = tid >> 7;             // row half 0/1
    int stid = tid & 127;
    int lane = tid & 31;
    int w2   = stid >> 5;            // warp-in-sub 0..3
    int r    = blockIdx.x * 2 + sub;
    int beg = off[r];
    int deg = off[r + 1] - beg;

    __shared__ float s_den[2][H];
    __shared__ float s_px[2][DMAX][H];
    __shared__ float s_mt[2][DMAX][4];
    __shared__ int   s_deg[2];

    if (stid < H) s_den[sub][stid] = 0.0f;
    if (stid == 0) s_deg[sub] = deg;
    __syncthreads();

    // q fragment: lane handles head lane>>2, 16 elems at offset lane*16
    float qf[16];
    {
        const uint4* qrow = (const uint4*)(qb + (size_t)r * C);
        uint4 u0 = qrow[lane * 2];
        uint4 u1 = qrow[lane * 2 + 1];
        unpack8(u0, qf);
        unpack8(u1, qf + 8);
    }

    float px0 = pos[r * 3 + 0], px1 = pos[r * 3 + 1], px2 = pos[r * 3 + 2];
    const int myh = lane >> 2;

    // ---- pass 1 ----
    for (int i0 = w2; i0 < deg; i0 += 4) {
        int e = eid[beg + i0];
        int ci = col_index[e];
        const uint4* krow = (const uint4*)(kb + (size_t)ci * C);
        uint4 k0 = krow[lane * 2];
        uint4 k1 = krow[lane * 2 + 1];
        float kf[16];
        unpack8(k0, kf);
        unpack8(k1, kf + 8);
        float s = 0.0f;
        #pragma unroll
        for (int j = 0; j < 16; j++) {
            float d = qf[j] - kf[j];
            s += d * d;
        }
        s += __shfl_xor_sync(0xffffffffu, s, 1);
        s += __shfl_xor_sync(0xffffffffu, s, 2);
        if ((lane & 3) == 0) {
            float val = __expf(-s * 0.125f + pab[(size_t)e * H + myh]);
            atomicAdd(&s_den[sub][myh], val);
            if (i0 < DMAX) s_px[sub][i0][myh] = val;
        }
        if (lane == 1 && i0 < DMAX) {
            int tci = to_col_index[e];
            float dinv = 1.0f / dist[e];
            s_mt[sub][i0][0] = __int_as_float(ci);
            s_mt[sub][i0][1] = (col_pos[tci * 3 + 0] - px0) * dinv;
            s_mt[sub][i0][2] = (col_pos[tci * 3 + 1] - px1) * dinv;
            s_mt[sub][i0][3] = (col_pos[tci * 3 + 2] - px2) * dinv;
        }
    }
    __syncthreads();
    if (stid < H) {
        float d = s_den[sub][stid];
        s_den[sub][stid] = (d == 0.0f) ? 1.0f : 1.0f / d;
    }
    __syncthreads();

    // ---- pass 2: channel-parallel aggregation ----
    int c0 = stid * 4;
    int hh = c0 >> 6;
    float4 wv0 = *(const float4*)(Wvec + c0);
    float4 wv1 = *(const float4*)(Wvec + C + c0);
    float4 wv2 = *(const float4*)(Wvec + 2 * C + c0);
    float4 bv  = *(const float4*)(bvec + c0);
    float dinvh = s_den[sub][hh];

    float a0 = 0.0f, a1 = 0.0f, a2 = 0.0f, a3 = 0.0f;
    int ncache = deg < DMAX ? deg : DMAX;
    int i = 0;
    for (; i + 4 <= ncache; i += 4) {
        int   ci[4];
        float rx[4], ry[4], rz[4], al[4];
        #pragma unroll
        for (int j = 0; j < 4; j++) {
            ci[j] = __float_as_int(s_mt[sub][i + j][0]);
            rx[j] = s_mt[sub][i + j][1];
            ry[j] = s_mt[sub][i + j][2];
            rz[j] = s_mt[sub][i + j][3];
            al[j] = s_px[sub][i + j][hh] * dinvh;
        }
        uint2 raw[4];
        #pragma unroll
        for (int j = 0; j < 4; j++)
            raw[j] = *(const uint2*)(vb + (size_t)ci[j] * C + c0);
        #pragma unroll
        for (int j = 0; j < 4; j++) {
            float2 f0 = __bfloat1622float2(*(__nv_bfloat162*)&raw[j].x);
            float2 f1 = __bfloat1622float2(*(__nv_bfloat162*)&raw[j].y);
            a0 += al[j] * (f0.x + rx[j] * wv0.x + ry[j] * wv1.x + rz[j] * wv2.x + bv.x);
            a1 += al[j] * (f0.y + rx[j] * wv0.y + ry[j] * wv1.y + rz[j] * wv2.y + bv.y);
            a2 += al[j] * (f1.x + rx[j] * wv0.z + ry[j] * wv1.z + rz[j] * wv2.z + bv.z);
            a3 += al[j] * (f1.y + rx[j] * wv0.w + ry[j] * wv1.w + rz[j] * wv2.w + bv.w);
        }
    }
    for (; i < ncache; i++) {
        int cii = __float_as_int(s_mt[sub][i][0]);
        float rxx = s_mt[sub][i][1], ryy = s_mt[sub][i][2], rzz = s_mt[sub][i][3];
        float all = s_px[sub][i][hh] * dinvh;
        uint2 raw = *(const uint2*)(vb + (size_t)cii * C + c0);
        float2 f0 = __bfloat1622float2(*(__nv_bfloat162*)&raw.x);
        float2 f1 = __bfloat1622float2(*(__nv_bfloat162*)&raw.y);
        a0 += all * (f0.x + rxx * wv0.x + ryy * wv1.x + rzz * wv2.x + bv.x);
        a1 += all * (f0.y + rxx * wv0.y + ryy * wv1.y + rzz * wv2.y + bv.y);
        a2 += all * (f1.x + rxx * wv0.z + ryy * wv1.z + rzz * wv2.z + bv.z);
        a3 += all * (f1.y + rxx * wv0.w + ryy * wv1.w + rzz * wv2.w + bv.w);
    }

    // overflow fallback (rare): loop to max degree of both rows, guarded
    int degmax = max(s_deg[0], s_deg[1]);
    for (int base = DMAX; base < degmax; base += 16) {
        int n = min(16, deg - base);   // may be <= 0 for this sub
        __syncthreads();
        if (n > 0) {
            for (int j = w2; j < n; j += 4) {
                int e = eid[beg + base + j];
                int ci = col_index[e];
                const uint4* krow = (const uint4*)(kb + (size_t)ci * C);
                uint4 k0 = krow[lane * 2];
                uint4 k1 = krow[lane * 2 + 1];
                float kf[16];
                unpack8(k0, kf);
                unpack8(k1, kf + 8);
                float s = 0.0f;
                #pragma unroll
                for (int jj = 0; jj < 16; jj++) {
                    float d = qf[jj] - kf[jj];
                    s += d * d;
                }
                s += __shfl_xor_sync(0xffffffffu, s, 1);
                s += __shfl_xor_sync(0xffffffffu, s, 2);
                if ((lane & 3) == 0)
                    s_px[sub][j][myh] = __expf(-s * 0.125f + pab[(size_t)e * H + myh]);
                if (lane == 1) {
                    int tci = to_col_index[e];
                    float dinv = 1.0f / dist[e];
                    s_mt[sub][j][0] = __int_as_float(ci);
                    s_mt[sub][j][1] = (col_pos[tci * 3 + 0] - px0) * dinv;
                    s_mt[sub][j][2] = (col_pos[tci * 3 + 1] - px1) * dinv;
                    s_mt[sub][j][3] = (col_pos[tci * 3 + 2] - px2) * dinv;
                }
            }
        }
        __syncthreads();
        for (int ii = 0; ii < n; ii++) {
            int cii = __float_as_int(s_mt[sub][ii][0]);
            float rxx = s_mt[sub][ii][1], ryy = s_mt[sub][ii][2], rzz = s_mt[sub][ii][3];
            float all = s_px[sub][ii][hh] * dinvh;
            uint2 raw = *(const uint2*)(vb + (size_t)cii * C + c0);
            float2 f0 = __bfloat1622float2(*(__nv_bfloat162*)&raw.x);
            float2 f1 = __bfloat1622float2(*(__nv_bfloat162*)&raw.y);
            a0 += all * (f0.x + rxx * wv0.x + ryy * wv1.x + rzz * wv2.x + bv.x);
            a1 += all * (f0.y + rxx * wv0.y + ryy * wv1.y + rzz * wv2.y + bv.y);
            a2 += all * (f1.x + rxx * wv0.z + ryy * wv1.z + rzz * wv2.z + bv.z);
            a3 += all * (f1.y + rxx * wv0.w + ryy * wv1.w + rzz * wv2.w + bv.w);
        }
    }

    __nv_bfloat162 o0 = __floats2bfloat162_rn(a0, a1);
    __nv_bfloat162 o1 = __floats2bfloat162_rn(a2, a3);
    __nv_bfloat162* ar = (__nv_bfloat162*)(agg + (size_t)r * C);
    ar[stid * 2]     = o0;
    ar[stid * 2 + 1] = o1;
}

// ---------------- launcher ----------------
extern "C" void kernel_launch(void* const* d_in, const int* in_sizes, int n_in,
                              void* d_out, int out_size) {
    const float* x        = (const float*)d_in[0];
    const int*   row_idx  = (const int*)  d_in[1];
    const int*   col_idx  = (const int*)  d_in[2];
    const int*   tcol_idx = (const int*)  d_in[3];
    const float* pab      = (const float*)d_in[5];
    const float* dist     = (const float*)d_in[6];
    const float* pos      = (const float*)d_in[7];
    const float* col_pos  = (const float*)d_in[8];
    const float* ln1_g    = (const float*)d_in[9];
    const float* ln1_b    = (const float*)d_in[10];
    const float* ln2_g    = (const float*)d_in[11];
    const float* ln2_b    = (const float*)d_in[12];
    const float* Wq       = (const float*)d_in[13];
    const float* bq       = (const float*)d_in[14];
    const float* Wk       = (const float*)d_in[15];
    const float* bk       = (const float*)d_in[16];
    const float* Wv       = (const float*)d_in[17];
    const float* bv       = (const float*)d_in[18];
    const float* Wvec     = (const float*)d_in[19];
    const float* bvec     = (const float*)d_in[20];
    const float* Wo       = (const float*)d_in[21];
    const float* bo       = (const float*)d_in[22];
    const float* W1       = (const float*)d_in[23];
    const float* b1       = (const float*)d_in[24];
    const float* W2       = (const float*)d_in[25];
    const float* b2       = (const float*)d_in[26];
    float* out = (float*)d_out;

    static __nv_bfloat16 *zp = nullptr, *qbp, *kbp, *vbp, *aggp, *z2p, *hidp,
                         *wqkvp, *wop, *w1p, *w2p;
    static float *x1p, *bqkvp;
    static int *cntp, *offp, *curp, *eidp;
    static cudaStream_t side = nullptr, side2 = nullptr;
    static cudaEvent_t evFork, evJoin, evLn, evW;
    if (!zp) {
        cudaGetSymbolAddress((void**)&zp,    g_z);
        cudaGetSymbolAddress((void**)&qbp,   g_qb);
        cudaGetSymbolAddress((void**)&kbp,   g_kb);
        cudaGetSymbolAddress((void**)&vbp,   g_vb);
        cudaGetSymbolAddress((void**)&aggp,  g_agg);
        cudaGetSymbolAddress((void**)&x1p,   g_x1);
        cudaGetSymbolAddress((void**)&z2p,   g_z2);
        cudaGetSymbolAddress((void**)&hidp,  g_hid);
        cudaGetSymbolAddress((void**)&wqkvp, g_wqkv);
        cudaGetSymbolAddress((void**)&bqkvp, g_bqkv);
        cudaGetSymbolAddress((void**)&wop,   g_wo);
        cudaGetSymbolAddress((void**)&w1p,   g_w1);
        cudaGetSymbolAddress((void**)&w2p,   g_w2);
        cudaGetSymbolAddress((void**)&cntp,  g_cnt);
        cudaGetSymbolAddress((void**)&offp,  g_off);
        cudaGetSymbolAddress((void**)&curp,  g_cur);
        cudaGetSymbolAddress((void**)&eidp,  g_eid);
        cudaFuncSetAttribute(tgemm_kernel<1>,
            cudaFuncAttributeMaxDynamicSharedMemorySize, SMEM_BYTES);
        cudaFuncSetAttribute(tgemm_kernel<2>,
            cudaFuncAttributeMaxDynamicSharedMemorySize, SMEM_BYTES);
        cudaFuncSetAttribute(tgemm_kernel<3>,
            cudaFuncAttributeMaxDynamicSharedMemorySize, SMEM_BYTES);
        cudaStreamCreateWithFlags(&side, cudaStreamNonBlocking);
        cudaStreamCreateWithFlags(&side2, cudaStreamNonBlocking);
        cudaEventCreateWithFlags(&evFork, cudaEventDisableTiming);
        cudaEventCreateWithFlags(&evJoin, cudaEventDisableTiming);
        cudaEventCreateWithFlags(&evLn,   cudaEventDisableTiming);
        cudaEventCreateWithFlags(&evW,    cudaEventDisableTiming);
    }

    // ---- fork ----
    cudaEventRecord(evFork, 0);
    cudaStreamWaitEvent(side, evFork, 0);
    cudaStreamWaitEvent(side2, evFork, 0);

    // side: CSR build (only feeds row_attn)
    zero_cnt_kernel<<<(L + 255) / 256, 256, 0, side>>>(cntp);
    hist_kernel<<<(E + 255) / 256, 256, 0, side>>>(row_idx, cntp);
    scan_kernel<<<1, 1024, 0, side>>>(cntp, offp, curp);
    scatter_kernel<<<(E + 255) / 256, 256, 0, side>>>(row_idx, curp, eidp);
    cudaEventRecord(evJoin, side);

    // side2: LN1, then the non-QKV weight transposes (overlap with QKV GEMM)
    ln_kernel<<<L, 128, 0, side2>>>(x, ln1_g, ln1_b, zp);
    cudaEventRecord(evLn, side2);
    transpose3_kernel<<<dim3(32, 32, 3), dim3(32, 8), 0, side2>>>(
        Wq, Wk, Wv, Wo, W1, W2, bq, bk, bv, wqkvp, wop, w1p, w2p, bqkvp, 3);
    cudaEventRecord(evW, side2);

    // main: QKV weight transposes only (critical path)
    transpose3_kernel<<<dim3(32, 32, 3), dim3(32, 8)>>>(
        Wq, Wk, Wv, Wo, W1, W2, bq, bk, bv, wqkvp, wop, w1p, w2p, bqkvp, 0);

    // QKV GEMM: needs z (LN1) + qkv weights; emits bf16 q/k/v planes
    cudaStreamWaitEvent(0, evLn, 0);
    dim3 gqkv(NQKV / BN, L / BM);
    tgemm_kernel<3><<<gqkv, 256, SMEM_BYTES>>>(zp, wqkvp, bqkvp, nullptr,
                                               nullptr, qbp, kbp, vbp,
                                               L, NQKV, C);

    // join CSR before row_attn (2 rows per block)
    cudaStreamWaitEvent(0, evJoin, 0);
    row_attn_kernel<<<L / 2, 256>>>(qbp, kbp, vbp, offp, eidp, col_idx,
                                    tcol_idx, pab, dist, pos, col_pos,
                                    Wvec, bvec, aggp);

    // join remaining weight transposes before Wo GEMM
    cudaStreamWaitEvent(0, evW, 0);
    dim3 g512(C / BN, L / BM);
    tgemm_kernel<2><<<g512, 256, SMEM_BYTES>>>(aggp, wop, bo, x, x1p,
                                               nullptr, nullptr, nullptr,
                                               L, C, C);

    ln_kernel<<<L, 128>>>(x1p, ln2_g, ln2_b, z2p);

    dim3 g1024(HID / BN, L / BM);
    tgemm_kernel<1><<<g1024, 256, SMEM_BYTES>>>(z2p, w1p, b1, nullptr,
                                                (float*)hidp,
                                                nullptr, nullptr, nullptr,
                                                L, HID, C);

    tgemm_kernel<2><<<g512, 256, SMEM_BYTES>>>(hidp, w2p, b2, x1p, out,
                                               nullptr, nullptr, nullptr,
                                               L, C, HID);
}

// round 14
// speedup vs baseline: 1.6081x; 1.6081x over previous
#include <cuda_runtime.h>
#include <cuda_bf16.h>
#include <math.h>
#include <stdint.h>

// Problem constants
#define L   16384
#define E   131072
#define SP  20000
#define C   512
#define H   8
#define DH  64
#define HID 1024
#define NQKV 1536

// ---------------- scratch (device globals: allocation-free) ----------------
__device__ __nv_bfloat16 g_z[(size_t)L * C];
__device__ __nv_bfloat16 g_qb[(size_t)L * C];
__device__ __nv_bfloat16 g_kb[(size_t)L * C];
__device__ __nv_bfloat16 g_vb[(size_t)L * C];
__device__ __nv_bfloat16 g_agg[(size_t)L * C];
__device__ float         g_x1[(size_t)L * C];
__device__ __nv_bfloat16 g_z2[(size_t)L * C];
__device__ __nv_bfloat16 g_hid[(size_t)L * HID];
// transposed bf16 weights: [N][K]
__device__ __nv_bfloat16 g_wqkv[(size_t)NQKV * C];
__device__ float         g_bqkv[NQKV];
__device__ __nv_bfloat16 g_wo[(size_t)C * C];
__device__ __nv_bfloat16 g_w1[(size_t)HID * C];
__device__ __nv_bfloat16 g_w2[(size_t)C * HID];
// CSR
__device__ int g_cnt[L];
__device__ int g_off[L + 1];
__device__ int g_cur[L];
__device__ int g_eid[E];

// ---------------- helpers ----------------
__device__ __forceinline__ float gelu_tanh(float x) {
    const float k0 = 0.7978845608028654f;
    const float k1 = 0.044715f;
    float x3 = x * x * x;
    return 0.5f * x * (1.0f + tanhf(k0 * (x + k1 * x3)));
}

__device__ __forceinline__ void mma_bf16(float* d, const uint32_t* a,
                                         const uint32_t* b) {
    asm volatile(
        "mma.sync.aligned.m16n8k16.row.col.f32.bf16.bf16.f32 "
        "{%0,%1,%2,%3}, {%4,%5,%6,%7}, {%8,%9}, {%0,%1,%2,%3};\n"
        : "+f"(d[0]), "+f"(d[1]), "+f"(d[2]), "+f"(d[3])
        : "r"(a[0]), "r"(a[1]), "r"(a[2]), "r"(a[3]),
          "r"(b[0]), "r"(b[1]));
}

__device__ __forceinline__ void ldsm_x4(uint32_t* r, uint32_t addr) {
    asm volatile(
        "ldmatrix.sync.aligned.m8n8.x4.shared.b16 {%0,%1,%2,%3}, [%4];\n"
        : "=r"(r[0]), "=r"(r[1]), "=r"(r[2]), "=r"(r[3]) : "r"(addr));
}

__device__ __forceinline__ void cp16(uint32_t dst, const void* src) {
    asm volatile("cp.async.cg.shared.global [%0], [%1], 16;\n"
                 :: "r"(dst), "l"(src));
}
__device__ __forceinline__ void cp_commit() {
    asm volatile("cp.async.commit_group;\n");
}
template <int N>
__device__ __forceinline__ void cp_wait() {
    asm volatile("cp.async.wait_group %0;\n" :: "n"(N));
}
__device__ __forceinline__ uint32_t smem_u32(const void* p) {
    uint32_t a;
    asm("{ .reg .u64 t; cvta.to.shared.u64 t, %1; cvt.u32.u64 %0, t; }"
        : "=r"(a) : "l"(p));
    return a;
}

// unpack uint4 (8 bf16) into 8 floats
__device__ __forceinline__ void unpack8(const uint4& u, float* f) {
    float2 t;
    t = __bfloat1622float2(*(const __nv_bfloat162*)&u.x); f[0] = t.x; f[1] = t.y;
    t = __bfloat1622float2(*(const __nv_bfloat162*)&u.y); f[2] = t.x; f[3] = t.y;
    t = __bfloat1622float2(*(const __nv_bfloat162*)&u.z); f[4] = t.x; f[5] = t.y;
    t = __bfloat1622float2(*(const __nv_bfloat162*)&u.w); f[6] = t.x; f[7] = t.y;
}

// swizzled byte offset of 16B chunk c (0..3) in logical row r
__device__ __forceinline__ uint32_t sw_off(int r, int c) {
    return (uint32_t)((r >> 1) * 128 + ((((c + 4 * (r & 1))) ^ ((r >> 1) & 7)) << 4));
}

// ---------------- weight prep: 3 transposes per launch + bias pack --------
// zbase=0: planes 0..2 (Wq,Wk,Wv -> wqkv) + bias pack  [grid (16,16,3)]
// zbase=3: planes 3..5 (Wo, W1, W2)                    [grid (32,32,3)]
__global__ void transpose3_kernel(const float* __restrict__ Wq,
                                  const float* __restrict__ Wk,
                                  const float* __restrict__ Wv,
                                  const float* __restrict__ Wo,
                                  const float* __restrict__ W1,
                                  const float* __restrict__ W2,
                                  const float* __restrict__ bq,
                                  const float* __restrict__ bk,
                                  const float* __restrict__ bv,
                                  __nv_bfloat16* __restrict__ wqkv,
                                  __nv_bfloat16* __restrict__ wo,
                                  __nv_bfloat16* __restrict__ w1,
                                  __nv_bfloat16* __restrict__ w2,
                                  float* __restrict__ bqkv,
                                  int zbase) {
    int z = zbase + blockIdx.z;
    if (z == 0) {
        int bid = blockIdx.y * gridDim.x + blockIdx.x;
        int i = bid * 256 + threadIdx.y * 32 + threadIdx.x;
        if (i < C) {
            bqkv[i]         = bq[i];
            bqkv[C + i]     = bk[i];
            bqkv[2 * C + i] = bv[i];
        }
    }
    const float* src;
    __nv_bfloat16* dst;
    int Kd, Nd;
    if (z == 0)      { src = Wq; dst = wqkv;                     Kd = C;   Nd = C; }
    else if (z == 1) { src = Wk; dst = wqkv + (size_t)C * C;     Kd = C;   Nd = C; }
    else if (z == 2) { src = Wv; dst = wqkv + (size_t)2 * C * C; Kd = C;   Nd = C; }
    else if (z == 3) { src = Wo; dst = wo;                       Kd = C;   Nd = C; }
    else if (z == 4) { src = W1; dst = w1;                       Kd = C;   Nd = HID; }
    else             { src = W2; dst = w2;                       Kd = HID; Nd = C; }
    int kb = blockIdx.y * 32, nb = blockIdx.x * 32;
    if (kb >= Kd || nb >= Nd) return;
    __shared__ float tile[32][33];
    int tx = threadIdx.x, ty = threadIdx.y;   // 32x8
    #pragma unroll
    for (int i = ty; i < 32; i += 8)
        tile[i][tx] = src[(size_t)(kb + i) * Nd + nb + tx];
    __syncthreads();
    #pragma unroll
    for (int i = ty; i < 32; i += 8)
        dst[(size_t)(nb + i) * Kd + kb + tx] = __float2bfloat16_rn(tile[tx][i]);
}

// ---------------- LayerNorm (bf16 output) ----------------
__global__ void ln_kernel(const float* __restrict__ x,
                          const float* __restrict__ g,
                          const float* __restrict__ b,
                          __nv_bfloat16* __restrict__ z) {
    int row = blockIdx.x;
    int t = threadIdx.x;                 // 0..127
    const float* xr = x + (size_t)row * C;
    float4 v4 = *(const float4*)(xr + t * 4);
    float s  = v4.x + v4.y + v4.z + v4.w;
    float ss = v4.x * v4.x + v4.y * v4.y + v4.z * v4.z + v4.w * v4.w;
    #pragma unroll
    for (int o = 16; o > 0; o >>= 1) {
        s  += __shfl_xor_sync(0xffffffffu, s, o);
        ss += __shfl_xor_sync(0xffffffffu, ss, o);
    }
    __shared__ float sh[4], sh2[4];
    int w = t >> 5;
    if ((t & 31) == 0) { sh[w] = s; sh2[w] = ss; }
    __syncthreads();
    float sum  = sh[0] + sh[1] + sh[2] + sh[3];
    float sum2 = sh2[0] + sh2[1] + sh2[2] + sh2[3];
    float mean = sum * (1.0f / C);
    float var  = sum2 * (1.0f / C) - mean * mean;
    float inv  = rsqrtf(var + 1e-5f);
    float4 g4 = *(const float4*)(g + t * 4);
    float4 b4 = *(const float4*)(b + t * 4);
    __nv_bfloat162 p0 = __floats2bfloat162_rn(
        (v4.x - mean) * inv * g4.x + b4.x, (v4.y - mean) * inv * g4.y + b4.y);
    __nv_bfloat162 p1 = __floats2bfloat162_rn(
        (v4.z - mean) * inv * g4.z + b4.z, (v4.w - mean) * inv * g4.w + b4.w);
    __nv_bfloat162* zr = (__nv_bfloat162*)(z + (size_t)row * C);
    zr[t * 2]     = p0;
    zr[t * 2 + 1] = p1;
}

// ---------------- bf16 tensor-core GEMM ----------------
// EPI: 1 bias+gelu->bf16, 2 bias+residual->fp32, 3 bias->bf16 q/k/v planes
#define BM  128
#define BN  128
#define BK  32
#define STAGES 4
#define STAGE_BYTES 8192
#define SMEM_BYTES (STAGES * 2 * STAGE_BYTES)   // 65536

template <int EPI>
__global__ __launch_bounds__(256, 2)
void tgemm_kernel(const __nv_bfloat16* __restrict__ A,
                  const __nv_bfloat16* __restrict__ B,
                  const float* __restrict__ bias, const float* __restrict__ res,
                  float* __restrict__ Cmat,
                  __nv_bfloat16* __restrict__ qb,
                  __nv_bfloat16* __restrict__ kb,
                  __nv_bfloat16* __restrict__ vb,
                  int M, int N, int K) {
    extern __shared__ float smemf[];
    const uint32_t sA = smem_u32(smemf);
    const uint32_t sB = sA + STAGES * STAGE_BYTES;

    const int tid    = threadIdx.x;
    const int lane   = tid & 31;
    const int wid    = tid >> 5;
    const int warp_m = wid & 3;
    const int warp_n = wid >> 2;

    const int brow = blockIdx.y * BM;
    const int bcol = blockIdx.x * BN;

    float acc[2][8][4];
    #pragma unroll
    for (int i = 0; i < 2; i++)
        #pragma unroll
        for (int j = 0; j < 8; j++)
            #pragma unroll
            for (int c = 0; c < 4; c++) acc[i][j][c] = 0.0f;

    const int lr = tid >> 1;
    const int c0 = (tid & 1) * 2;
    const __nv_bfloat16* A0 = A + (size_t)(brow + lr) * K + c0 * 8;
    const __nv_bfloat16* B0 = B + (size_t)(bcol + lr) * K + c0 * 8;
    const uint32_t dA0 = sA + sw_off(lr, c0);
    const uint32_t dA1 = sA + sw_off(lr, c0 + 1);
    const uint32_t dB0 = sB + sw_off(lr, c0);
    const uint32_t dB1 = sB + sw_off(lr, c0 + 1);

    const int m8    = lane >> 3;
    const int rowin = lane & 7;
    int rA[2], cAh = m8 >> 1;
    rA[0] = warp_m * 32 + (m8 & 1) * 8 + rowin;
    rA[1] = rA[0] + 16;
    int rB[4], cBh = m8 & 1;
    #pragma unroll
    for (int np = 0; np < 4; np++)
        rB[np] = warp_n * 64 + np * 16 + (m8 >> 1) * 8 + rowin;

    const int kIters = K / BK;

    #pragma unroll
    for (int s = 0; s < STAGES - 1; s++) {
        int k0 = s * BK;
        uint32_t so = (uint32_t)s * STAGE_BYTES;
        cp16(dA0 + so, A0 + k0);
        cp16(dA1 + so, A0 + k0 + 8);
        cp16(dB0 + so, B0 + k0);
        cp16(dB1 + so, B0 + k0 + 8);
        cp_commit();
    }

    int buf = 0;
    int nbuf = STAGES - 1;
    for (int s = 0; s < kIters; s++) {
        cp_wait<STAGES - 2>();
        __syncthreads();

        if (s + STAGES - 1 < kIters) {
            int k0 = (s + STAGES - 1) * BK;
            uint32_t so = (uint32_t)nbuf * STAGE_BYTES;
            cp16(dA0 + so, A0 + k0);
            cp16(dA1 + so, A0 + k0 + 8);
            cp16(dB0 + so, B0 + k0);
            cp16(dB1 + so, B0 + k0 + 8);
        }
        cp_commit();

        const uint32_t aBuf = sA + (uint32_t)buf * STAGE_BYTES;
        const uint32_t bBuf = sB + (uint32_t)buf * STAGE_BYTES;
        #pragma unroll
        for (int ks = 0; ks < 2; ks++) {
            uint32_t af[2][4];
            #pragma unroll
            for (int mt = 0; mt < 2; mt++)
                ldsm_x4(af[mt], aBuf + sw_off(rA[mt], 2 * ks + cAh));
            #pragma unroll
            for (int np = 0; np < 4; np++) {
                uint32_t bf[4];
                ldsm_x4(bf, bBuf + sw_off(rB[np], 2 * ks + cBh));
                mma_bf16(acc[0][2 * np],     af[0], bf);
                mma_bf16(acc[1][2 * np],     af[1], bf);
                mma_bf16(acc[0][2 * np + 1], af[0], bf + 2);
                mma_bf16(acc[1][2 * np + 1], af[1], bf + 2);
            }
        }
        buf = (buf + 1 == STAGES) ? 0 : buf + 1;
        nbuf = (nbuf + 1 == STAGES) ? 0 : nbuf + 1;
    }

    const int grp = lane >> 2;
    const int t4  = lane & 3;
    #pragma unroll
    for (int mt = 0; mt < 2; mt++) {
        int row = brow + warp_m * 32 + mt * 16 + grp;
        #pragma unroll
        for (int nt = 0; nt < 8; nt++) {
            int col = bcol + warp_n * 64 + nt * 8 + 2 * t4;
            float b0 = bias[col], b1 = bias[col + 1];
            float v0 = acc[mt][nt][0] + b0;
            float v1 = acc[mt][nt][1] + b1;
            float v2 = acc[mt][nt][2] + b0;
            float v3 = acc[mt][nt][3] + b1;
            if (EPI == 1) {
                __nv_bfloat16* O = (__nv_bfloat16*)Cmat;
                __nv_bfloat162 o0 = __floats2bfloat162_rn(gelu_tanh(v0),
                                                          gelu_tanh(v1));
                __nv_bfloat162 o1 = __floats2bfloat162_rn(gelu_tanh(v2),
                                                          gelu_tanh(v3));
                *(__nv_bfloat162*)&O[(size_t)row * N + col]       = o0;
                *(__nv_bfloat162*)&O[(size_t)(row + 8) * N + col] = o1;
            } else if (EPI == 3) {
                __nv_bfloat162 p0 = __floats2bfloat162_rn(v0, v1);
                __nv_bfloat162 p1 = __floats2bfloat162_rn(v2, v3);
                __nv_bfloat16* dst;
                int cc;
                if (col < C)          { dst = qb; cc = col; }
                else if (col < 2 * C) { dst = kb; cc = col - C; }
                else                  { dst = vb; cc = col - 2 * C; }
                *(__nv_bfloat162*)&dst[(size_t)row * C + cc]       = p0;
                *(__nv_bfloat162*)&dst[(size_t)(row + 8) * C + cc] = p1;
            } else {
                if (EPI == 2) {
                    v0 += res[(size_t)row * N + col];
                    v1 += res[(size_t)row * N + col + 1];
                    v2 += res[(size_t)(row + 8) * N + col];
                    v3 += res[(size_t)(row + 8) * N + col + 1];
                }
                float2 o0 = { v0, v1 };
                float2 o1 = { v2, v3 };
                *(float2*)&Cmat[(size_t)row * N + col]       = o0;
                *(float2*)&Cmat[(size_t)(row + 8) * N + col] = o1;
            }
        }
    }
}

// ---------------- CSR build ----------------
__global__ void zero_cnt_kernel(int* __restrict__ cnt) {
    int i = blockIdx.x * blockDim.x + threadIdx.x;
    if (i < L) cnt[i] = 0;
}
__global__ void hist_kernel(const int* __restrict__ row, int* __restrict__ cnt) {
    int e = blockIdx.x * blockDim.x + threadIdx.x;
    if (e < E) atomicAdd(&cnt[row[e]], 1);
}
__global__ void scan_kernel(const int* __restrict__ cnt, int* __restrict__ off,
                            int* __restrict__ cur) {
    __shared__ int ws[32];
    int tid = threadIdx.x;
    int base = tid * 16;
    int loc[16];
    int s = 0;
    #pragma unroll
    for (int i = 0; i < 16; i++) { loc[i] = s; s += cnt[base + i]; }
    int lane = tid & 31, w = tid >> 5;
    int v = s;
    #pragma unroll
    for (int o = 1; o < 32; o <<= 1) {
        int t = __shfl_up_sync(0xffffffffu, v, o);
        if (lane >= o) v += t;
    }
    if (lane == 31) ws[w] = v;
    __syncthreads();
    if (w == 0) {
        int t = ws[lane];
        #pragma unroll
        for (int o = 1; o < 32; o <<= 1) {
            int u = __shfl_up_sync(0xffffffffu, t, o);
            if (lane >= o) t += u;
        }
        ws[lane] = t;
    }
    __syncthreads();
    int excl = v - s + (w > 0 ? ws[w - 1] : 0);
    #pragma unroll
    for (int i = 0; i < 16; i++) {
        off[base + i] = excl + loc[i];
        cur[base + i] = excl + loc[i];
    }
    if (tid == 1023) off[L] = excl + s;
}
__global__ void scatter_kernel(const int* __restrict__ row,
                               int* __restrict__ cur, int* __restrict__ eid) {
    int e = blockIdx.x * blockDim.x + threadIdx.x;
    if (e < E) {
        int p = atomicAdd(&cur[row[e]], 1);
        eid[p] = e;
    }
}

// ---------------- fused edge attention (R12 version: 1 row / 128 thr) -----
#define DMAX 64
__global__ __launch_bounds__(128)
void row_attn_kernel(const __nv_bfloat16* __restrict__ qb,
                     const __nv_bfloat16* __restrict__ kb,
                     const __nv_bfloat16* __restrict__ vb,
                     const int* __restrict__ off,
                     const int* __restrict__ eid,
                     const int* __restrict__ col_index,
                     const int* __restrict__ to_col_index,
                     const float* __restrict__ pab,
                     const float* __restrict__ dist,
                     const float* __restrict__ pos,
                     const float* __restrict__ col_pos,
                     const float* __restrict__ Wvec,
                     const float* __restrict__ bvec,
                     __nv_bfloat16* __restrict__ agg) {
    int r = blockIdx.x;
    int tid = threadIdx.x;          // 128
    int lane = tid & 31;
    int w = tid >> 5;               // warp 0..3
    int beg = off[r];
    int deg = off[r + 1] - beg;

    __shared__ float s_den[H];
    __shared__ float s_px[DMAX][H];
    __shared__ float s_mt[DMAX][4];

    if (tid < H) s_den[tid] = 0.0f;
    __syncthreads();

    // q fragment: lane handles head lane>>2, 16 elems at offset lane*16
    float qf[16];
    {
        const uint4* qrow = (const uint4*)(qb + (size_t)r * C);
        uint4 u0 = qrow[lane * 2];
        uint4 u1 = qrow[lane * 2 + 1];
        unpack8(u0, qf);
        unpack8(u1, qf + 8);
    }

    float px0 = pos[r * 3 + 0], px1 = pos[r * 3 + 1], px2 = pos[r * 3 + 2];
    const int myh = lane >> 2;

    // ---- pass 1: scores; den; cache pexp/meta ----
    for (int i0 = w; i0 < deg; i0 += 4) {
        int e = eid[beg + i0];
        int ci = col_index[e];
        const uint4* krow = (const uint4*)(kb + (size_t)ci * C);
        uint4 k0 = krow[lane * 2];
        uint4 k1 = krow[lane * 2 + 1];
        float kf[16];
        unpack8(k0, kf);
        unpack8(k1, kf + 8);
        float s = 0.0f;
        #pragma unroll
        for (int j = 0; j < 16; j++) {
            float d = qf[j] - kf[j];
            s += d * d;
        }
        s += __shfl_xor_sync(0xffffffffu, s, 1);
        s += __shfl_xor_sync(0xffffffffu, s, 2);
        if ((lane & 3) == 0) {
            float val = __expf(-s * 0.125f + pab[(size_t)e * H + myh]);
            atomicAdd(&s_den[myh], val);
            if (i0 < DMAX) s_px[i0][myh] = val;
        }
        if (lane == 1 && i0 < DMAX) {
            int tci = to_col_index[e];
            float dinv = 1.0f / dist[e];
            s_mt[i0][0] = __int_as_float(ci);
            s_mt[i0][1] = (col_pos[tci * 3 + 0] - px0) * dinv;
            s_mt[i0][2] = (col_pos[tci * 3 + 1] - px1) * dinv;
            s_mt[i0][3] = (col_pos[tci * 3 + 2] - px2) * dinv;
        }
    }
    __syncthreads();
    if (tid < H) {
        float d = s_den[tid];
        s_den[tid] = (d == 0.0f) ? 1.0f : 1.0f / d;
    }
    __syncthreads();

    // ---- pass 2: channel-parallel aggregation, 4-edge pipeline, bf16 v ----
    int c0 = tid * 4;
    int hh = c0 >> 6;
    float4 wv0 = *(const float4*)(Wvec + c0);
    float4 wv1 = *(const float4*)(Wvec + C + c0);
    float4 wv2 = *(const float4*)(Wvec + 2 * C + c0);
    float4 bv  = *(const float4*)(bvec + c0);
    float dinvh = s_den[hh];

    float a0 = 0.0f, a1 = 0.0f, a2 = 0.0f, a3 = 0.0f;
    int ncache = deg < DMAX ? deg : DMAX;
    int i = 0;
    for (; i + 4 <= ncache; i += 4) {
        int   ci[4];
        float rx[4], ry[4], rz[4], al[4];
        #pragma unroll
        for (int j = 0; j < 4; j++) {
            ci[j] = __float_as_int(s_mt[i + j][0]);
            rx[j] = s_mt[i + j][1];
            ry[j] = s_mt[i + j][2];
            rz[j] = s_mt[i + j][3];
            al[j] = s_px[i + j][hh] * dinvh;
        }
        uint2 raw[4];
        #pragma unroll
        for (int j = 0; j < 4; j++)
            raw[j] = *(const uint2*)(vb + (size_t)ci[j] * C + c0);
        #pragma unroll
        for (int j = 0; j < 4; j++) {
            float2 f0 = __bfloat1622float2(*(__nv_bfloat162*)&raw[j].x);
            float2 f1 = __bfloat1622float2(*(__nv_bfloat162*)&raw[j].y);
            a0 += al[j] * (f0.x + rx[j] * wv0.x + ry[j] * wv1.x + rz[j] * wv2.x + bv.x);
            a1 += al[j] * (f0.y + rx[j] * wv0.y + ry[j] * wv1.y + rz[j] * wv2.y + bv.y);
            a2 += al[j] * (f1.x + rx[j] * wv0.z + ry[j] * wv1.z + rz[j] * wv2.z + bv.z);
            a3 += al[j] * (f1.y + rx[j] * wv0.w + ry[j] * wv1.w + rz[j] * wv2.w + bv.w);
        }
    }
    for (; i < ncache; i++) {
        int cii = __float_as_int(s_mt[i][0]);
        float rxx = s_mt[i][1], ryy = s_mt[i][2], rzz = s_mt[i][3];
        float all = s_px[i][hh] * dinvh;
        uint2 raw = *(const uint2*)(vb + (size_t)cii * C + c0);
        float2 f0 = __bfloat1622float2(*(__nv_bfloat162*)&raw.x);
        float2 f1 = __bfloat1622float2(*(__nv_bfloat162*)&raw.y);
        a0 += all * (f0.x + rxx * wv0.x + ryy * wv1.x + rzz * wv2.x + bv.x);
        a1 += all * (f0.y + rxx * wv0.y + ryy * wv1.y + rzz * wv2.y + bv.y);
        a2 += all * (f1.x + rxx * wv0.z + ryy * wv1.z + rzz * wv2.z + bv.z);
        a3 += all * (f1.y + rxx * wv0.w + ryy * wv1.w + rzz * wv2.w + bv.w);
    }
    // overflow fallback (deg > DMAX): recompute scores in chunks of 16
    for (int base = DMAX; base < deg; base += 16) {
        int n = min(16, deg - base);
        __syncthreads();
        for (int j = w; j < n; j += 4) {
            int e = eid[beg + base + j];
            int ci = col_index[e];
            const uint4* krow = (const uint4*)(kb + (size_t)ci * C);
            uint4 k0 = krow[lane * 2];
            uint4 k1 = krow[lane * 2 + 1];
            float kf[16];
            unpack8(k0, kf);
            unpack8(k1, kf + 8);
            float s = 0.0f;
            #pragma unroll
            for (int jj = 0; jj < 16; jj++) {
                float d = qf[jj] - kf[jj];
                s += d * d;
            }
            s += __shfl_xor_sync(0xffffffffu, s, 1);
            s += __shfl_xor_sync(0xffffffffu, s, 2);
            if ((lane & 3) == 0)
                s_px[j][myh] = __expf(-s * 0.125f + pab[(size_t)e * H + myh]);
            if (lane == 1) {
                int tci = to_col_index[e];
                float dinv = 1.0f / dist[e];
                s_mt[j][0] = __int_as_float(ci);
                s_mt[j][1] = (col_pos[tci * 3 + 0] - px0) * dinv;
                s_mt[j][2] = (col_pos[tci * 3 + 1] - px1) * dinv;
                s_mt[j][3] = (col_pos[tci * 3 + 2] - px2) * dinv;
            }
        }
        __syncthreads();
        for (int ii = 0; ii < n; ii++) {
            int cii = __float_as_int(s_mt[ii][0]);
            float rxx = s_mt[ii][1], ryy = s_mt[ii][2], rzz = s_mt[ii][3];
            float all = s_px[ii][hh] * dinvh;
            uint2 raw = *(const uint2*)(vb + (size_t)cii * C + c0);
            float2 f0 = __bfloat1622float2(*(__nv_bfloat162*)&raw.x);
            float2 f1 = __bfloat1622float2(*(__nv_bfloat162*)&raw.y);
            a0 += all * (f0.x + rxx * wv0.x + ryy * wv1.x + rzz * wv2.x + bv.x);
            a1 += all * (f0.y + rxx * wv0.y + ryy * wv1.y + rzz * wv2.y + bv.y);
            a2 += all * (f1.x + rxx * wv0.z + ryy * wv1.z + rzz * wv2.z + bv.z);
            a3 += all * (f1.y + rxx * wv0.w + ryy * wv1.w + rzz * wv2.w + bv.w);
        }
    }

    __nv_bfloat162 o0 = __floats2bfloat162_rn(a0, a1);
    __nv_bfloat162 o1 = __floats2bfloat162_rn(a2, a3);
    __nv_bfloat162* ar = (__nv_bfloat162*)(agg + (size_t)r * C);
    ar[tid * 2]     = o0;
    ar[tid * 2 + 1] = o1;
}

// ---------------- launcher ----------------
extern "C" void kernel_launch(void* const* d_in, const int* in_sizes, int n_in,
                              void* d_out, int out_size) {
    const float* x        = (const float*)d_in[0];
    const int*   row_idx  = (const int*)  d_in[1];
    const int*   col_idx  = (const int*)  d_in[2];
    const int*   tcol_idx = (const int*)  d_in[3];
    const float* pab      = (const float*)d_in[5];
    const float* dist     = (const float*)d_in[6];
    const float* pos      = (const float*)d_in[7];
    const float* col_pos  = (const float*)d_in[8];
    const float* ln1_g    = (const float*)d_in[9];
    const float* ln1_b    = (const float*)d_in[10];
    const float* ln2_g    = (const float*)d_in[11];
    const float* ln2_b    = (const float*)d_in[12];
    const float* Wq       = (const float*)d_in[13];
    const float* bq       = (const float*)d_in[14];
    const float* Wk       = (const float*)d_in[15];
    const float* bk       = (const float*)d_in[16];
    const float* Wv       = (const float*)d_in[17];
    const float* bv       = (const float*)d_in[18];
    const float* Wvec     = (const float*)d_in[19];
    const float* bvec     = (const float*)d_in[20];
    const float* Wo       = (const float*)d_in[21];
    const float* bo       = (const float*)d_in[22];
    const float* W1       = (const float*)d_in[23];
    const float* b1       = (const float*)d_in[24];
    const float* W2       = (const float*)d_in[25];
    const float* b2       = (const float*)d_in[26];
    float* out = (float*)d_out;

    static __nv_bfloat16 *zp = nullptr, *qbp, *kbp, *vbp, *aggp, *z2p, *hidp,
                         *wqkvp, *wop, *w1p, *w2p;
    static float *x1p, *bqkvp;
    static int *cntp, *offp, *curp, *eidp;
    static cudaStream_t side = nullptr, side2 = nullptr;
    static cudaEvent_t evFork, evJoin, evLn, evW;
    if (!zp) {
        cudaGetSymbolAddress((void**)&zp,    g_z);
        cudaGetSymbolAddress((void**)&qbp,   g_qb);
        cudaGetSymbolAddress((void**)&kbp,   g_kb);
        cudaGetSymbolAddress((void**)&vbp,   g_vb);
        cudaGetSymbolAddress((void**)&aggp,  g_agg);
        cudaGetSymbolAddress((void**)&x1p,   g_x1);
        cudaGetSymbolAddress((void**)&z2p,   g_z2);
        cudaGetSymbolAddress((void**)&hidp,  g_hid);
        cudaGetSymbolAddress((void**)&wqkvp, g_wqkv);
        cudaGetSymbolAddress((void**)&bqkvp, g_bqkv);
        cudaGetSymbolAddress((void**)&wop,   g_wo);
        cudaGetSymbolAddress((void**)&w1p,   g_w1);
        cudaGetSymbolAddress((void**)&w2p,   g_w2);
        cudaGetSymbolAddress((void**)&cntp,  g_cnt);
        cudaGetSymbolAddress((void**)&offp,  g_off);
        cudaGetSymbolAddress((void**)&curp,  g_cur);
        cudaGetSymbolAddress((void**)&eidp,  g_eid);
        cudaFuncSetAttribute(tgemm_kernel<1>,
            cudaFuncAttributeMaxDynamicSharedMemorySize, SMEM_BYTES);
        cudaFuncSetAttribute(tgemm_kernel<2>,
            cudaFuncAttributeMaxDynamicSharedMemorySize, SMEM_BYTES);
        cudaFuncSetAttribute(tgemm_kernel<3>,
            cudaFuncAttributeMaxDynamicSharedMemorySize, SMEM_BYTES);
        cudaStreamCreateWithFlags(&side, cudaStreamNonBlocking);
        cudaStreamCreateWithFlags(&side2, cudaStreamNonBlocking);
        cudaEventCreateWithFlags(&evFork, cudaEventDisableTiming);
        cudaEventCreateWithFlags(&evJoin, cudaEventDisableTiming);
        cudaEventCreateWithFlags(&evLn,   cudaEventDisableTiming);
        cudaEventCreateWithFlags(&evW,    cudaEventDisableTiming);
    }

    // ---- fork ----
    cudaEventRecord(evFork, 0);
    cudaStreamWaitEvent(side, evFork, 0);
    cudaStreamWaitEvent(side2, evFork, 0);

    // side: CSR build (only feeds row_attn)
    zero_cnt_kernel<<<(L + 255) / 256, 256, 0, side>>>(cntp);
    hist_kernel<<<(E + 255) / 256, 256, 0, side>>>(row_idx, cntp);
    scan_kernel<<<1, 1024, 0, side>>>(cntp, offp, curp);
    scatter_kernel<<<(E + 255) / 256, 256, 0, side>>>(row_idx, curp, eidp);
    cudaEventRecord(evJoin, side);

    // side2: LN1, then the non-QKV weight transposes (overlap with QKV GEMM)
    ln_kernel<<<L, 128, 0, side2>>>(x, ln1_g, ln1_b, zp);
    cudaEventRecord(evLn, side2);
    transpose3_kernel<<<dim3(32, 32, 3), dim3(32, 8), 0, side2>>>(
        Wq, Wk, Wv, Wo, W1, W2, bq, bk, bv, wqkvp, wop, w1p, w2p, bqkvp, 3);
    cudaEventRecord(evW, side2);

    // main: QKV weight transposes only (tight grid, critical path)
    transpose3_kernel<<<dim3(16, 16, 3), dim3(32, 8)>>>(
        Wq, Wk, Wv, Wo, W1, W2, bq, bk, bv, wqkvp, wop, w1p, w2p, bqkvp, 0);

    // QKV GEMM: needs z (LN1) + qkv weights; emits bf16 q/k/v planes
    cudaStreamWaitEvent(0, evLn, 0);
    dim3 gqkv(NQKV / BN, L / BM);
    tgemm_kernel<3><<<gqkv, 256, SMEM_BYTES>>>(zp, wqkvp, bqkvp, nullptr,
                                               nullptr, qbp, kbp, vbp,
                                               L, NQKV, C);

    // join CSR before row_attn (R12 config: 1 row per 128-thr block)
    cudaStreamWaitEvent(0, evJoin, 0);
    row_attn_kernel<<<L, 128>>>(qbp, kbp, vbp, offp, eidp, col_idx, tcol_idx,
                                pab, dist, pos, col_pos, Wvec, bvec, aggp);

    // join remaining weight transposes before Wo GEMM
    cudaStreamWaitEvent(0, evW, 0);
    dim3 g512(C / BN, L / BM);
    tgemm_kernel<2><<<g512, 256, SMEM_BYTES>>>(aggp, wop, bo, x, x1p,
                                               nullptr, nullptr, nullptr,
                                               L, C, C);

    ln_kernel<<<L, 128>>>(x1p, ln2_g, ln2_b, z2p);

    dim3 g1024(HID / BN, L / BM);
    tgemm_kernel<1><<<g1024, 256, SMEM_BYTES>>>(z2p, w1p, b1, nullptr,
                                                (float*)hidp,
                                                nullptr, nullptr, nullptr,
                                                L, HID, C);

    tgemm_kernel<2><<<g512, 256, SMEM_BYTES>>>(hidp, w2p, b2, x1p, out,
                                               nullptr, nullptr, nullptr,
                                               L, C, HID);
}

// round 15
// speedup vs baseline: 1.7170x; 1.0677x over previous
#include <cuda_runtime.h>
#include <cuda_bf16.h>
#include <math.h>
#include <stdint.h>

// Problem constants
#define L   16384
#define E   131072
#define SP  20000
#define C   512
#define H   8
#define DH  64
#define HID 1024
#define NQKV 1536

// ---------------- scratch (device globals: allocation-free) ----------------
__device__ __nv_bfloat16 g_z[(size_t)L * C];
__device__ __nv_bfloat16 g_qb[(size_t)L * C];
__device__ __nv_bfloat16 g_kb[(size_t)L * C];
__device__ __nv_bfloat16 g_vb[(size_t)L * C];
__device__ __nv_bfloat16 g_agg[(size_t)L * C];
__device__ float         g_x1[(size_t)L * C];
__device__ __nv_bfloat16 g_z2[(size_t)L * C];
__device__ __nv_bfloat16 g_hid[(size_t)L * HID];
// transposed bf16 weights: [N][K]
__device__ __nv_bfloat16 g_wqkv[(size_t)NQKV * C];
__device__ float         g_bqkv[NQKV];
__device__ __nv_bfloat16 g_wo[(size_t)C * C];
__device__ __nv_bfloat16 g_w1[(size_t)HID * C];
__device__ __nv_bfloat16 g_w2[(size_t)C * HID];
// CSR
__device__ int g_cnt[L];
__device__ int g_off[L + 1];
__device__ int g_cur[L];
__device__ int g_eid[E];

// ---------------- helpers ----------------
__device__ __forceinline__ float gelu_tanh(float x) {
    const float k0 = 0.7978845608028654f;
    const float k1 = 0.044715f;
    float x3 = x * x * x;
    return 0.5f * x * (1.0f + tanhf(k0 * (x + k1 * x3)));
}

__device__ __forceinline__ void mma_bf16(float* d, const uint32_t* a,
                                         const uint32_t* b) {
    asm volatile(
        "mma.sync.aligned.m16n8k16.row.col.f32.bf16.bf16.f32 "
        "{%0,%1,%2,%3}, {%4,%5,%6,%7}, {%8,%9}, {%0,%1,%2,%3};\n"
        : "+f"(d[0]), "+f"(d[1]), "+f"(d[2]), "+f"(d[3])
        : "r"(a[0]), "r"(a[1]), "r"(a[2]), "r"(a[3]),
          "r"(b[0]), "r"(b[1]));
}

__device__ __forceinline__ void ldsm_x4(uint32_t* r, uint32_t addr) {
    asm volatile(
        "ldmatrix.sync.aligned.m8n8.x4.shared.b16 {%0,%1,%2,%3}, [%4];\n"
        : "=r"(r[0]), "=r"(r[1]), "=r"(r[2]), "=r"(r[3]) : "r"(addr));
}

__device__ __forceinline__ void cp16(uint32_t dst, const void* src) {
    asm volatile("cp.async.cg.shared.global [%0], [%1], 16;\n"
                 :: "r"(dst), "l"(src));
}
__device__ __forceinline__ void cp_commit() {
    asm volatile("cp.async.commit_group;\n");
}
template <int N>
__device__ __forceinline__ void cp_wait() {
    asm volatile("cp.async.wait_group %0;\n" :: "n"(N));
}
__device__ __forceinline__ uint32_t smem_u32(const void* p) {
    uint32_t a;
    asm("{ .reg .u64 t; cvta.to.shared.u64 t, %1; cvt.u32.u64 %0, t; }"
        : "=r"(a) : "l"(p));
    return a;
}

// unpack uint4 (8 bf16) into 8 floats
__device__ __forceinline__ void unpack8(const uint4& u, float* f) {
    float2 t;
    t = __bfloat1622float2(*(const __nv_bfloat162*)&u.x); f[0] = t.x; f[1] = t.y;
    t = __bfloat1622float2(*(const __nv_bfloat162*)&u.y); f[2] = t.x; f[3] = t.y;
    t = __bfloat1622float2(*(const __nv_bfloat162*)&u.z); f[4] = t.x; f[5] = t.y;
    t = __bfloat1622float2(*(const __nv_bfloat162*)&u.w); f[6] = t.x; f[7] = t.y;
}

// swizzled byte offset of 16B chunk c (0..3) in logical row r
__device__ __forceinline__ uint32_t sw_off(int r, int c) {
    return (uint32_t)((r >> 1) * 128 + ((((c + 4 * (r & 1))) ^ ((r >> 1) & 7)) << 4));
}

// ---------------- weight prep: all 6 transposes + bias pack ---------------
__global__ void transpose_all_kernel(const float* __restrict__ Wq,
                                     const float* __restrict__ Wk,
                                     const float* __restrict__ Wv,
                                     const float* __restrict__ Wo,
                                     const float* __restrict__ W1,
                                     const float* __restrict__ W2,
                                     const float* __restrict__ bq,
                                     const float* __restrict__ bk,
                                     const float* __restrict__ bv,
                                     __nv_bfloat16* __restrict__ wqkv,
                                     __nv_bfloat16* __restrict__ wo,
                                     __nv_bfloat16* __restrict__ w1,
                                     __nv_bfloat16* __restrict__ w2,
                                     float* __restrict__ bqkv) {
    int z = blockIdx.z;
    if (z == 0) {
        int bid = blockIdx.y * gridDim.x + blockIdx.x;
        int i = bid * 256 + threadIdx.y * 32 + threadIdx.x;
        if (i < C) {
            bqkv[i]         = bq[i];
            bqkv[C + i]     = bk[i];
            bqkv[2 * C + i] = bv[i];
        }
    }
    const float* src;
    __nv_bfloat16* dst;
    int Kd, Nd;
    if (z == 0)      { src = Wq; dst = wqkv;                     Kd = C;   Nd = C; }
    else if (z == 1) { src = Wk; dst = wqkv + (size_t)C * C;     Kd = C;   Nd = C; }
    else if (z == 2) { src = Wv; dst = wqkv + (size_t)2 * C * C; Kd = C;   Nd = C; }
    else if (z == 3) { src = Wo; dst = wo;                       Kd = C;   Nd = C; }
    else if (z == 4) { src = W1; dst = w1;                       Kd = C;   Nd = HID; }
    else             { src = W2; dst = w2;                       Kd = HID; Nd = C; }
    int kb = blockIdx.y * 32, nb = blockIdx.x * 32;
    if (kb >= Kd || nb >= Nd) return;
    __shared__ float tile[32][33];
    int tx = threadIdx.x, ty = threadIdx.y;   // 32x8
    #pragma unroll
    for (int i = ty; i < 32; i += 8)
        tile[i][tx] = src[(size_t)(kb + i) * Nd + nb + tx];
    __syncthreads();
    #pragma unroll
    for (int i = ty; i < 32; i += 8)
        dst[(size_t)(nb + i) * Kd + kb + tx] = __float2bfloat16_rn(tile[tx][i]);
}

// ---------------- LayerNorm (bf16 output), row base offset ----------------
__global__ void ln_kernel(const float* __restrict__ x,
                          const float* __restrict__ g,
                          const float* __restrict__ b,
                          __nv_bfloat16* __restrict__ z, int rbase) {
    int row = blockIdx.x + rbase;
    int t = threadIdx.x;                 // 0..127
    const float* xr = x + (size_t)row * C;
    float4 v4 = *(const float4*)(xr + t * 4);
    float s  = v4.x + v4.y + v4.z + v4.w;
    float ss = v4.x * v4.x + v4.y * v4.y + v4.z * v4.z + v4.w * v4.w;
    #pragma unroll
    for (int o = 16; o > 0; o >>= 1) {
        s  += __shfl_xor_sync(0xffffffffu, s, o);
        ss += __shfl_xor_sync(0xffffffffu, ss, o);
    }
    __shared__ float sh[4], sh2[4];
    int w = t >> 5;
    if ((t & 31) == 0) { sh[w] = s; sh2[w] = ss; }
    __syncthreads();
    float sum  = sh[0] + sh[1] + sh[2] + sh[3];
    float sum2 = sh2[0] + sh2[1] + sh2[2] + sh2[3];
    float mean = sum * (1.0f / C);
    float var  = sum2 * (1.0f / C) - mean * mean;
    float inv  = rsqrtf(var + 1e-5f);
    float4 g4 = *(const float4*)(g + t * 4);
    float4 b4 = *(const float4*)(b + t * 4);
    __nv_bfloat162 p0 = __floats2bfloat162_rn(
        (v4.x - mean) * inv * g4.x + b4.x, (v4.y - mean) * inv * g4.y + b4.y);
    __nv_bfloat162 p1 = __floats2bfloat162_rn(
        (v4.z - mean) * inv * g4.z + b4.z, (v4.w - mean) * inv * g4.w + b4.w);
    __nv_bfloat162* zr = (__nv_bfloat162*)(z + (size_t)row * C);
    zr[t * 2]     = p0;
    zr[t * 2 + 1] = p1;
}

// ---------------- bf16 tensor-core GEMM (row base offset) -----------------
// EPI: 1 bias+gelu->bf16, 2 bias+residual->fp32, 3 bias->bf16 q/k/v planes
#define BM  128
#define BN  128
#define BK  32
#define STAGES 4
#define STAGE_BYTES 8192
#define SMEM_BYTES (STAGES * 2 * STAGE_BYTES)   // 65536

template <int EPI>
__global__ __launch_bounds__(256, 2)
void tgemm_kernel(const __nv_bfloat16* __restrict__ A,
                  const __nv_bfloat16* __restrict__ B,
                  const float* __restrict__ bias, const float* __restrict__ res,
                  float* __restrict__ Cmat,
                  __nv_bfloat16* __restrict__ qb,
                  __nv_bfloat16* __restrict__ kb,
                  __nv_bfloat16* __restrict__ vb,
                  int M, int N, int K, int rowbase) {
    extern __shared__ float smemf[];
    const uint32_t sA = smem_u32(smemf);
    const uint32_t sB = sA + STAGES * STAGE_BYTES;

    const int tid    = threadIdx.x;
    const int lane   = tid & 31;
    const int wid    = tid >> 5;
    const int warp_m = wid & 3;
    const int warp_n = wid >> 2;

    const int brow = blockIdx.y * BM + rowbase;
    const int bcol = blockIdx.x * BN;

    float acc[2][8][4];
    #pragma unroll
    for (int i = 0; i < 2; i++)
        #pragma unroll
        for (int j = 0; j < 8; j++)
            #pragma unroll
            for (int c = 0; c < 4; c++) acc[i][j][c] = 0.0f;

    const int lr = tid >> 1;
    const int c0 = (tid & 1) * 2;
    const __nv_bfloat16* A0 = A + (size_t)(brow + lr) * K + c0 * 8;
    const __nv_bfloat16* B0 = B + (size_t)(bcol + lr) * K + c0 * 8;
    const uint32_t dA0 = sA + sw_off(lr, c0);
    const uint32_t dA1 = sA + sw_off(lr, c0 + 1);
    const uint32_t dB0 = sB + sw_off(lr, c0);
    const uint32_t dB1 = sB + sw_off(lr, c0 + 1);

    const int m8    = lane >> 3;
    const int rowin = lane & 7;
    int rA[2], cAh = m8 >> 1;
    rA[0] = warp_m * 32 + (m8 & 1) * 8 + rowin;
    rA[1] = rA[0] + 16;
    int rB[4], cBh = m8 & 1;
    #pragma unroll
    for (int np = 0; np < 4; np++)
        rB[np] = warp_n * 64 + np * 16 + (m8 >> 1) * 8 + rowin;

    const int kIters = K / BK;

    #pragma unroll
    for (int s = 0; s < STAGES - 1; s++) {
        int k0 = s * BK;
        uint32_t so = (uint32_t)s * STAGE_BYTES;
        cp16(dA0 + so, A0 + k0);
        cp16(dA1 + so, A0 + k0 + 8);
        cp16(dB0 + so, B0 + k0);
        cp16(dB1 + so, B0 + k0 + 8);
        cp_commit();
    }

    int buf = 0;
    int nbuf = STAGES - 1;
    for (int s = 0; s < kIters; s++) {
        cp_wait<STAGES - 2>();
        __syncthreads();

        if (s + STAGES - 1 < kIters) {
            int k0 = (s + STAGES - 1) * BK;
            uint32_t so = (uint32_t)nbuf * STAGE_BYTES;
            cp16(dA0 + so, A0 + k0);
            cp16(dA1 + so, A0 + k0 + 8);
            cp16(dB0 + so, B0 + k0);
            cp16(dB1 + so, B0 + k0 + 8);
        }
        cp_commit();

        const uint32_t aBuf = sA + (uint32_t)buf * STAGE_BYTES;
        const uint32_t bBuf = sB + (uint32_t)buf * STAGE_BYTES;
        #pragma unroll
        for (int ks = 0; ks < 2; ks++) {
            uint32_t af[2][4];
            #pragma unroll
            for (int mt = 0; mt < 2; mt++)
                ldsm_x4(af[mt], aBuf + sw_off(rA[mt], 2 * ks + cAh));
            #pragma unroll
            for (int np = 0; np < 4; np++) {
                uint32_t bf[4];
                ldsm_x4(bf, bBuf + sw_off(rB[np], 2 * ks + cBh));
                mma_bf16(acc[0][2 * np],     af[0], bf);
                mma_bf16(acc[1][2 * np],     af[1], bf);
                mma_bf16(acc[0][2 * np + 1], af[0], bf + 2);
                mma_bf16(acc[1][2 * np + 1], af[1], bf + 2);
            }
        }
        buf = (buf + 1 == STAGES) ? 0 : buf + 1;
        nbuf = (nbuf + 1 == STAGES) ? 0 : nbuf + 1;
    }

    const int grp = lane >> 2;
    const int t4  = lane & 3;
    #pragma unroll
    for (int mt = 0; mt < 2; mt++) {
        int row = brow + warp_m * 32 + mt * 16 + grp;
        #pragma unroll
        for (int nt = 0; nt < 8; nt++) {
            int col = bcol + warp_n * 64 + nt * 8 + 2 * t4;
            float b0 = bias[col], b1 = bias[col + 1];
            float v0 = acc[mt][nt][0] + b0;
            float v1 = acc[mt][nt][1] + b1;
            float v2 = acc[mt][nt][2] + b0;
            float v3 = acc[mt][nt][3] + b1;
            if (EPI == 1) {
                __nv_bfloat16* O = (__nv_bfloat16*)Cmat;
                __nv_bfloat162 o0 = __floats2bfloat162_rn(gelu_tanh(v0),
                                                          gelu_tanh(v1));
                __nv_bfloat162 o1 = __floats2bfloat162_rn(gelu_tanh(v2),
                                                          gelu_tanh(v3));
                *(__nv_bfloat162*)&O[(size_t)row * N + col]       = o0;
                *(__nv_bfloat162*)&O[(size_t)(row + 8) * N + col] = o1;
            } else if (EPI == 3) {
                __nv_bfloat162 p0 = __floats2bfloat162_rn(v0, v1);
                __nv_bfloat162 p1 = __floats2bfloat162_rn(v2, v3);
                __nv_bfloat16* dst;
                int cc;
                if (col < C)          { dst = qb; cc = col; }
                else if (col < 2 * C) { dst = kb; cc = col - C; }
                else                  { dst = vb; cc = col - 2 * C; }
                *(__nv_bfloat162*)&dst[(size_t)row * C + cc]       = p0;
                *(__nv_bfloat162*)&dst[(size_t)(row + 8) * C + cc] = p1;
            } else {
                if (EPI == 2) {
                    v0 += res[(size_t)row * N + col];
                    v1 += res[(size_t)row * N + col + 1];
                    v2 += res[(size_t)(row + 8) * N + col];
                    v3 += res[(size_t)(row + 8) * N + col + 1];
                }
                float2 o0 = { v0, v1 };
                float2 o1 = { v2, v3 };
                *(float2*)&Cmat[(size_t)row * N + col]       = o0;
                *(float2*)&Cmat[(size_t)(row + 8) * N + col] = o1;
            }
        }
    }
}

// ---------------- CSR build ----------------
__global__ void zero_cnt_kernel(int* __restrict__ cnt) {
    int i = blockIdx.x * blockDim.x + threadIdx.x;
    if (i < L) cnt[i] = 0;
}
__global__ void hist_kernel(const int* __restrict__ row, int* __restrict__ cnt) {
    int e = blockIdx.x * blockDim.x + threadIdx.x;
    if (e < E) atomicAdd(&cnt[row[e]], 1);
}
__global__ void scan_kernel(const int* __restrict__ cnt, int* __restrict__ off,
                            int* __restrict__ cur) {
    __shared__ int ws[32];
    int tid = threadIdx.x;
    int base = tid * 16;
    int loc[16];
    int s = 0;
    #pragma unroll
    for (int i = 0; i < 16; i++) { loc[i] = s; s += cnt[base + i]; }
    int lane = tid & 31, w = tid >> 5;
    int v = s;
    #pragma unroll
    for (int o = 1; o < 32; o <<= 1) {
        int t = __shfl_up_sync(0xffffffffu, v, o);
        if (lane >= o) v += t;
    }
    if (lane == 31) ws[w] = v;
    __syncthreads();
    if (w == 0) {
        int t = ws[lane];
        #pragma unroll
        for (int o = 1; o < 32; o <<= 1) {
            int u = __shfl_up_sync(0xffffffffu, t, o);
            if (lane >= o) t += u;
        }
        ws[lane] = t;
    }
    __syncthreads();
    int excl = v - s + (w > 0 ? ws[w - 1] : 0);
    #pragma unroll
    for (int i = 0; i < 16; i++) {
        off[base + i] = excl + loc[i];
        cur[base + i] = excl + loc[i];
    }
    if (tid == 1023) off[L] = excl + s;
}
__global__ void scatter_kernel(const int* __restrict__ row,
                               int* __restrict__ cur, int* __restrict__ eid) {
    int e = blockIdx.x * blockDim.x + threadIdx.x;
    if (e < E) {
        int p = atomicAdd(&cur[row[e]], 1);
        eid[p] = e;
    }
}

// ---------------- fused edge attention (1 row / 128 thr, row base) --------
#define DMAX 64
__global__ __launch_bounds__(128)
void row_attn_kernel(const __nv_bfloat16* __restrict__ qb,
                     const __nv_bfloat16* __restrict__ kb,
                     const __nv_bfloat16* __restrict__ vb,
                     const int* __restrict__ off,
                     const int* __restrict__ eid,
                     const int* __restrict__ col_index,
                     const int* __restrict__ to_col_index,
                     const float* __restrict__ pab,
                     const float* __restrict__ dist,
                     const float* __restrict__ pos,
                     const float* __restrict__ col_pos,
                     const float* __restrict__ Wvec,
                     const float* __restrict__ bvec,
                     __nv_bfloat16* __restrict__ agg, int rbase) {
    int r = blockIdx.x + rbase;
    int tid = threadIdx.x;          // 128
    int lane = tid & 31;
    int w = tid >> 5;               // warp 0..3
    int beg = off[r];
    int deg = off[r + 1] - beg;

    __shared__ float s_den[H];
    __shared__ float s_px[DMAX][H];
    __shared__ float s_mt[DMAX][4];

    if (tid < H) s_den[tid] = 0.0f;
    __syncthreads();

    float qf[16];
    {
        const uint4* qrow = (const uint4*)(qb + (size_t)r * C);
        uint4 u0 = qrow[lane * 2];
        uint4 u1 = qrow[lane * 2 + 1];
        unpack8(u0, qf);
        unpack8(u1, qf + 8);
    }

    float px0 = pos[r * 3 + 0], px1 = pos[r * 3 + 1], px2 = pos[r * 3 + 2];
    const int myh = lane >> 2;

    // ---- pass 1 ----
    for (int i0 = w; i0 < deg; i0 += 4) {
        int e = eid[beg + i0];
        int ci = col_index[e];
        const uint4* krow = (const uint4*)(kb + (size_t)ci * C);
        uint4 k0 = krow[lane * 2];
        uint4 k1 = krow[lane * 2 + 1];
        float kf[16];
        unpack8(k0, kf);
        unpack8(k1, kf + 8);
        float s = 0.0f;
        #pragma unroll
        for (int j = 0; j < 16; j++) {
            float d = qf[j] - kf[j];
            s += d * d;
        }
        s += __shfl_xor_sync(0xffffffffu, s, 1);
        s += __shfl_xor_sync(0xffffffffu, s, 2);
        if ((lane & 3) == 0) {
            float val = __expf(-s * 0.125f + pab[(size_t)e * H + myh]);
            atomicAdd(&s_den[myh], val);
            if (i0 < DMAX) s_px[i0][myh] = val;
        }
        if (lane == 1 && i0 < DMAX) {
            int tci = to_col_index[e];
            float dinv = 1.0f / dist[e];
            s_mt[i0][0] = __int_as_float(ci);
            s_mt[i0][1] = (col_pos[tci * 3 + 0] - px0) * dinv;
            s_mt[i0][2] = (col_pos[tci * 3 + 1] - px1) * dinv;
            s_mt[i0][3] = (col_pos[tci * 3 + 2] - px2) * dinv;
        }
    }
    __syncthreads();
    if (tid < H) {
        float d = s_den[tid];
        s_den[tid] = (d == 0.0f) ? 1.0f : 1.0f / d;
    }
    __syncthreads();

    // ---- pass 2 ----
    int c0 = tid * 4;
    int hh = c0 >> 6;
    float4 wv0 = *(const float4*)(Wvec + c0);
    float4 wv1 = *(const float4*)(Wvec + C + c0);
    float4 wv2 = *(const float4*)(Wvec + 2 * C + c0);
    float4 bv  = *(const float4*)(bvec + c0);
    float dinvh = s_den[hh];

    float a0 = 0.0f, a1 = 0.0f, a2 = 0.0f, a3 = 0.0f;
    int ncache = deg < DMAX ? deg : DMAX;
    int i = 0;
    for (; i + 4 <= ncache; i += 4) {
        int   ci[4];
        float rx[4], ry[4], rz[4], al[4];
        #pragma unroll
        for (int j = 0; j < 4; j++) {
            ci[j] = __float_as_int(s_mt[i + j][0]);
            rx[j] = s_mt[i + j][1];
            ry[j] = s_mt[i + j][2];
            rz[j] = s_mt[i + j][3];
            al[j] = s_px[i + j][hh] * dinvh;
        }
        uint2 raw[4];
        #pragma unroll
        for (int j = 0; j < 4; j++)
            raw[j] = *(const uint2*)(vb + (size_t)ci[j] * C + c0);
        #pragma unroll
        for (int j = 0; j < 4; j++) {
            float2 f0 = __bfloat1622float2(*(__nv_bfloat162*)&raw[j].x);
            float2 f1 = __bfloat1622float2(*(__nv_bfloat162*)&raw[j].y);
            a0 += al[j] * (f0.x + rx[j] * wv0.x + ry[j] * wv1.x + rz[j] * wv2.x + bv.x);
            a1 += al[j] * (f0.y + rx[j] * wv0.y + ry[j] * wv1.y + rz[j] * wv2.y + bv.y);
            a2 += al[j] * (f1.x + rx[j] * wv0.z + ry[j] * wv1.z + rz[j] * wv2.z + bv.z);
            a3 += al[j] * (f1.y + rx[j] * wv0.w + ry[j] * wv1.w + rz[j] * wv2.w + bv.w);
        }
    }
    for (; i < ncache; i++) {
        int cii = __float_as_int(s_mt[i][0]);
        float rxx = s_mt[i][1], ryy = s_mt[i][2], rzz = s_mt[i][3];
        float all = s_px[i][hh] * dinvh;
        uint2 raw = *(const uint2*)(vb + (size_t)cii * C + c0);
        float2 f0 = __bfloat1622float2(*(__nv_bfloat162*)&raw.x);
        float2 f1 = __bfloat1622float2(*(__nv_bfloat162*)&raw.y);
        a0 += all * (f0.x + rxx * wv0.x + ryy * wv1.x + rzz * wv2.x + bv.x);
        a1 += all * (f0.y + rxx * wv0.y + ryy * wv1.y + rzz * wv2.y + bv.y);
        a2 += all * (f1.x + rxx * wv0.z + ryy * wv1.z + rzz * wv2.z + bv.z);
        a3 += all * (f1.y + rxx * wv0.w + ryy * wv1.w + rzz * wv2.w + bv.w);
    }
    // overflow fallback (deg > DMAX)
    for (int base = DMAX; base < deg; base += 16) {
        int n = min(16, deg - base);
        __syncthreads();
        for (int j = w; j < n; j += 4) {
            int e = eid[beg + base + j];
            int ci = col_index[e];
            const uint4* krow = (const uint4*)(kb + (size_t)ci * C);
            uint4 k0 = krow[lane * 2];
            uint4 k1 = krow[lane * 2 + 1];
            float kf[16];
            unpack8(k0, kf);
            unpack8(k1, kf + 8);
            float s = 0.0f;
            #pragma unroll
            for (int jj = 0; jj < 16; jj++) {
                float d = qf[jj] - kf[jj];
                s += d * d;
            }
            s += __shfl_xor_sync(0xffffffffu, s, 1);
            s += __shfl_xor_sync(0xffffffffu, s, 2);
            if ((lane & 3) == 0)
                s_px[j][myh] = __expf(-s * 0.125f + pab[(size_t)e * H + myh]);
            if (lane == 1) {
                int tci = to_col_index[e];
                float dinv = 1.0f / dist[e];
                s_mt[j][0] = __int_as_float(ci);
                s_mt[j][1] = (col_pos[tci * 3 + 0] - px0) * dinv;
                s_mt[j][2] = (col_pos[tci * 3 + 1] - px1) * dinv;
                s_mt[j][3] = (col_pos[tci * 3 + 2] - px2) * dinv;
            }
        }
        __syncthreads();
        for (int ii = 0; ii < n; ii++) {
            int cii = __float_as_int(s_mt[ii][0]);
            float rxx = s_mt[ii][1], ryy = s_mt[ii][2], rzz = s_mt[ii][3];
            float all = s_px[ii][hh] * dinvh;
            uint2 raw = *(const uint2*)(vb + (size_t)cii * C + c0);
            float2 f0 = __bfloat1622float2(*(__nv_bfloat162*)&raw.x);
            float2 f1 = __bfloat1622float2(*(__nv_bfloat162*)&raw.y);
            a0 += all * (f0.x + rxx * wv0.x + ryy * wv1.x + rzz * wv2.x + bv.x);
            a1 += all * (f0.y + rxx * wv0.y + ryy * wv1.y + rzz * wv2.y + bv.y);
            a2 += all * (f1.x + rxx * wv0.z + ryy * wv1.z + rzz * wv2.z + bv.z);
            a3 += all * (f1.y + rxx * wv0.w + ryy * wv1.w + rzz * wv2.w + bv.w);
        }
    }

    __nv_bfloat162 o0 = __floats2bfloat162_rn(a0, a1);
    __nv_bfloat162 o1 = __floats2bfloat162_rn(a2, a3);
    __nv_bfloat162* ar = (__nv_bfloat162*)(agg + (size_t)r * C);
    ar[tid * 2]     = o0;
    ar[tid * 2 + 1] = o1;
}

// ---------------- launcher ----------------
extern "C" void kernel_launch(void* const* d_in, const int* in_sizes, int n_in,
                              void* d_out, int out_size) {
    const float* x        = (const float*)d_in[0];
    const int*   row_idx  = (const int*)  d_in[1];
    const int*   col_idx  = (const int*)  d_in[2];
    const int*   tcol_idx = (const int*)  d_in[3];
    const float* pab      = (const float*)d_in[5];
    const float* dist     = (const float*)d_in[6];
    const float* pos      = (const float*)d_in[7];
    const float* col_pos  = (const float*)d_in[8];
    const float* ln1_g    = (const float*)d_in[9];
    const float* ln1_b    = (const float*)d_in[10];
    const float* ln2_g    = (const float*)d_in[11];
    const float* ln2_b    = (const float*)d_in[12];
    const float* Wq       = (const float*)d_in[13];
    const float* bq       = (const float*)d_in[14];
    const float* Wk       = (const float*)d_in[15];
    const float* bk       = (const float*)d_in[16];
    const float* Wv       = (const float*)d_in[17];
    const float* bv       = (const float*)d_in[18];
    const float* Wvec     = (const float*)d_in[19];
    const float* bvec     = (const float*)d_in[20];
    const float* Wo       = (const float*)d_in[21];
    const float* bo       = (const float*)d_in[22];
    const float* W1       = (const float*)d_in[23];
    const float* b1       = (const float*)d_in[24];
    const float* W2       = (const float*)d_in[25];
    const float* b2       = (const float*)d_in[26];
    float* out = (float*)d_out;

    static __nv_bfloat16 *zp = nullptr, *qbp, *kbp, *vbp, *aggp, *z2p, *hidp,
                         *wqkvp, *wop, *w1p, *w2p;
    static float *x1p, *bqkvp;
    static int *cntp, *offp, *curp, *eidp;
    static cudaStream_t side = nullptr, side2 = nullptr;
    static cudaEvent_t evFork, evJoin, evLn, evQKV, evDone;
    if (!zp) {
        cudaGetSymbolAddress((void**)&zp,    g_z);
        cudaGetSymbolAddress((void**)&qbp,   g_qb);
        cudaGetSymbolAddress((void**)&kbp,   g_kb);
        cudaGetSymbolAddress((void**)&vbp,   g_vb);
        cudaGetSymbolAddress((void**)&aggp,  g_agg);
        cudaGetSymbolAddress((void**)&x1p,   g_x1);
        cudaGetSymbolAddress((void**)&z2p,   g_z2);
        cudaGetSymbolAddress((void**)&hidp,  g_hid);
        cudaGetSymbolAddress((void**)&wqkvp, g_wqkv);
        cudaGetSymbolAddress((void**)&bqkvp, g_bqkv);
        cudaGetSymbolAddress((void**)&wop,   g_wo);
        cudaGetSymbolAddress((void**)&w1p,   g_w1);
        cudaGetSymbolAddress((void**)&w2p,   g_w2);
        cudaGetSymbolAddress((void**)&cntp,  g_cnt);
        cudaGetSymbolAddress((void**)&offp,  g_off);
        cudaGetSymbolAddress((void**)&curp,  g_cur);
        cudaGetSymbolAddress((void**)&eidp,  g_eid);
        cudaFuncSetAttribute(tgemm_kernel<1>,
            cudaFuncAttributeMaxDynamicSharedMemorySize, SMEM_BYTES);
        cudaFuncSetAttribute(tgemm_kernel<2>,
            cudaFuncAttributeMaxDynamicSharedMemorySize, SMEM_BYTES);
        cudaFuncSetAttribute(tgemm_kernel<3>,
            cudaFuncAttributeMaxDynamicSharedMemorySize, SMEM_BYTES);
        cudaStreamCreateWithFlags(&side, cudaStreamNonBlocking);
        cudaStreamCreateWithFlags(&side2, cudaStreamNonBlocking);
        cudaEventCreateWithFlags(&evFork, cudaEventDisableTiming);
        cudaEventCreateWithFlags(&evJoin, cudaEventDisableTiming);
        cudaEventCreateWithFlags(&evLn,   cudaEventDisableTiming);
        cudaEventCreateWithFlags(&evQKV,  cudaEventDisableTiming);
        cudaEventCreateWithFlags(&evDone, cudaEventDisableTiming);
    }

    const int HL = L / 2;   // 8192 rows per half-chain
    dim3 gHalf512(C / BN, HL / BM);     // (4,64)
    dim3 gHalf1024(HID / BN, HL / BM);  // (8,64)

    // ---- fork ----
    cudaEventRecord(evFork, 0);
    cudaStreamWaitEvent(side, evFork, 0);
    cudaStreamWaitEvent(side2, evFork, 0);

    // side: CSR build
    zero_cnt_kernel<<<(L + 255) / 256, 256, 0, side>>>(cntp);
    hist_kernel<<<(E + 255) / 256, 256, 0, side>>>(row_idx, cntp);
    scan_kernel<<<1, 1024, 0, side>>>(cntp, offp, curp);
    scatter_kernel<<<(E + 255) / 256, 256, 0, side>>>(row_idx, curp, eidp);
    cudaEventRecord(evJoin, side);

    // side2: LN1
    ln_kernel<<<L, 128, 0, side2>>>(x, ln1_g, ln1_b, zp, 0);
    cudaEventRecord(evLn, side2);

    // main: all weight transposes (concurrent with LN1)
    transpose_all_kernel<<<dim3(32, 32, 6), dim3(32, 8)>>>(
        Wq, Wk, Wv, Wo, W1, W2, bq, bk, bv, wqkvp, wop, w1p, w2p, bqkvp);

    // QKV GEMM (full) — needs z + qkv weights
    cudaStreamWaitEvent(0, evLn, 0);
    dim3 gqkv(NQKV / BN, L / BM);
    tgemm_kernel<3><<<gqkv, 256, SMEM_BYTES>>>(zp, wqkvp, bqkvp, nullptr,
                                               nullptr, qbp, kbp, vbp,
                                               L, NQKV, C, 0);
    cudaEventRecord(evQKV, 0);

    // ---- two-chain row-pipelined tail ----
    // chain 0 (main): rows [0, HL)
    cudaStreamWaitEvent(0, evJoin, 0);
    row_attn_kernel<<<HL, 128>>>(qbp, kbp, vbp, offp, eidp, col_idx,
                                 tcol_idx, pab, dist, pos, col_pos,
                                 Wvec, bvec, aggp, 0);
    tgemm_kernel<2><<<gHalf512, 256, SMEM_BYTES>>>(aggp, wop, bo, x, x1p,
                                                   nullptr, nullptr, nullptr,
                                                   L, C, C, 0);
    ln_kernel<<<HL, 128>>>(x1p, ln2_g, ln2_b, z2p, 0);
    tgemm_kernel<1><<<gHalf1024, 256, SMEM_BYTES>>>(z2p, w1p, b1, nullptr,
                                                    (float*)hidp,
                                                    nullptr, nullptr, nullptr,
                                                    L, HID, C, 0);
    tgemm_kernel<2><<<gHalf512, 256, SMEM_BYTES>>>(hidp, w2p, b2, x1p, out,
                                                   nullptr, nullptr, nullptr,
                                                   L, C, HID, 0);

    // chain 1 (side): rows [HL, L)  — CSR already in-stream; wait QKV
    cudaStreamWaitEvent(side, evQKV, 0);
    row_attn_kernel<<<HL, 128, 0, side>>>(qbp, kbp, vbp, offp, eidp, col_idx,
                                          tcol_idx, pab, dist, pos, col_pos,
                                          Wvec, bvec, aggp, HL);
    tgemm_kernel<2><<<gHalf512, 256, SMEM_BYTES, side>>>(
        aggp, wop, bo, x, x1p, nullptr, nullptr, nullptr, L, C, C, HL);
    ln_kernel<<<HL, 128, 0, side>>>(x1p, ln2_g, ln2_b, z2p, HL);
    tgemm_kernel<1><<<gHalf1024, 256, SMEM_BYTES, side>>>(
        z2p, w1p, b1, nullptr, (float*)hidp, nullptr, nullptr, nullptr,
        L, HID, C, HL);
    tgemm_kernel<2><<<gHalf512, 256, SMEM_BYTES, side>>>(
        hidp, w2p, b2, x1p, out, nullptr, nullptr, nullptr, L, C, HID, HL);
    cudaEventRecord(evDone, side);

    // final join
    cudaStreamWaitEvent(0, evDone, 0);
}